// round 3
// baseline (speedup 1.0000x reference)
#include <cuda_runtime.h>
#include <math.h>

// Problem constants (fixed by setup_inputs)
namespace {
constexpr int BB = 2;
constexpr int LL = 1024;
constexpr int CC = 1024;
constexpr int HH = 8;
constexpr int DD = 128;   // CC / HH
constexpr int SS = 32;    // sample taps
constexpr int KK = 64;    // kernel taps
constexpr int BL = BB * LL;           // 2048
constexpr int HK = HH * KK;           // 512
}

// ---------------- scratch (static device globals; no runtime allocation) ----
__device__ float g_freq [BL * HH];        // [B*L, H]
__device__ float g_phase[BL * HH];        // [B*L, H]
__device__ float g_kmat [BL * HK];        // [B*L, H*K]  (4 MB)
__device__ float g_y    [BL * CC];        // [B*L, C]    (8 MB)
__device__ float g_wt_out[CC * CC];       // out_w transposed  [k][n]
__device__ float g_wt_ker[CC * HK];       // kernel_w transposed [k][n]

// ---------------- XLA/Eigen fast-tanh f32 ------------------------------------
__device__ __forceinline__ float tanh_xla(float x) {
    float xc = fminf(fmaxf(x, -7.99881172180175781f), 7.99881172180175781f);
    float x2 = __fmul_rn(xc, xc);
    float p = __fmaf_rn(x2, -2.76076847742355e-16f, 2.00018790482477e-13f);
    p = __fmaf_rn(x2, p, -8.60467152213735e-11f);
    p = __fmaf_rn(x2, p,  5.12229709037114e-08f);
    p = __fmaf_rn(x2, p,  1.48572235717979e-05f);
    p = __fmaf_rn(x2, p,  6.37261928875436e-04f);
    p = __fmaf_rn(x2, p,  4.89352455891786e-03f);
    p = __fmul_rn(xc, p);
    float q = __fmaf_rn(x2, 1.19825839466702e-06f, 1.18534705686654e-04f);
    q = __fmaf_rn(x2, q, 2.26843463243900e-03f);
    q = __fmaf_rn(x2, q, 4.89352518554385e-03f);
    float r = __fdiv_rn(p, q);
    return (fabsf(x) < 0.0004f) ? x : r;
}

// ---------------- transpose: in[rows][cols] -> out[cols][rows] --------------
__global__ void transpose_kernel(const float* __restrict__ in,
                                 float* __restrict__ out,
                                 int rows, int cols) {
    __shared__ float tile[32][33];
    int c0 = blockIdx.x * 32;
    int r0 = blockIdx.y * 32;
    int tx = threadIdx.x;           // 0..31
    int ty = threadIdx.y;           // 0..7
    #pragma unroll
    for (int i = ty; i < 32; i += 8)
        tile[i][tx] = in[(size_t)(r0 + i) * cols + (c0 + tx)];
    __syncthreads();
    #pragma unroll
    for (int i = ty; i < 32; i += 8)
        out[(size_t)(c0 + i) * rows + (r0 + tx)] = tile[tx][i];
}

// ---------------- wave: sequential-FMA dots -> freq/phase -------------------
// Downstream elementwise math uses STRICT unfused mul/add matching XLA's
// lowering (no fp contraction at HLO level): freq = 1 + sig*15 as mul,add.
__global__ void __launch_bounds__(128) wave_exact_kernel(
    const float* __restrict__ x,
    const float* __restrict__ wave_w,   // [16, C]
    const float* __restrict__ wave_b)   // [16] (zeros)
{
    __shared__ float xs[8][CC];
    __shared__ float wv[8][16];
    const int bl0 = blockIdx.x * 8;
    for (int i = threadIdx.x; i < 8 * CC / 4; i += 128) {
        int r = i >> 8;             // CC/4 = 256 float4 per row
        int c4 = i & 255;
        ((float4*)xs[r])[c4] = ((const float4*)(x + (size_t)(bl0 + r) * CC))[c4];
    }
    __syncthreads();

    const int rl = threadIdx.x >> 4;   // 0..7 local row
    const int j  = threadIdx.x & 15;   // 0..15 output index
    const float* wr = wave_w + j * CC;
    const float* xr = xs[rl];
    float acc = 0.0f;
    for (int k = 0; k < CC; k++)
        acc = __fmaf_rn(xr[k], __ldg(wr + k), acc);   // serial chain, fixed order
    acc = __fadd_rn(acc, __ldg(wave_b + j));
    wv[rl][j] = acc;
    __syncthreads();

    if (threadIdx.x < 64) {
        int r = threadIdx.x >> 3;
        int h = threadIdx.x & 7;
        float w0 = wv[r][2 * h];
        float w1 = wv[r][2 * h + 1];
        // sigmoid = 0.5 + 0.5 * tanh(0.5 * x)  (XLA logistic expansion)
        float t0  = tanh_xla(__fmul_rn(0.5f, w0));
        float sig = __fadd_rn(0.5f, __fmul_rn(0.5f, t0));
        // freq = 1 + sig*15  -- STRICT mul then add (no fma; XLA does not fuse)
        float freq = __fadd_rn(1.0f, __fmul_rn(sig, 15.0f));
        float t1 = tanh_xla(w1);
        float phase = __fmul_rn(t1, freq);
        g_freq [(bl0 + r) * HH + h] = freq;
        g_phase[(bl0 + r) * HH + h] = phase;
    }
}

// ---------------- generic fp32 SGEMM: C = A[MxK] * B[KxN] (+bias[n]) --------
template <int BM, int BN, int TM, int TN>
__global__ void __launch_bounds__(256) sgemm_kernel(
    const float* __restrict__ A, const float* __restrict__ Bm,
    const float* __restrict__ bias, float* __restrict__ C,
    int M, int N, int K)
{
    constexpr int BK = 16;
    static_assert((BM / TM) * (BN / TN) == 256, "thread count");
    __shared__ float As[BK][BM];
    __shared__ float Bs[BK][BN];

    const int tid = threadIdx.x;
    const int m0 = blockIdx.y * BM;
    const int n0 = blockIdx.x * BN;
    const int tmg = tid / (BN / TN);
    const int tng = tid % (BN / TN);

    float acc[TM][TN];
    #pragma unroll
    for (int i = 0; i < TM; i++)
        #pragma unroll
        for (int j = 0; j < TN; j++) acc[i][j] = 0.0f;

    for (int k0 = 0; k0 < K; k0 += BK) {
        #pragma unroll
        for (int it = tid; it < BM * BK / 4; it += 256) {
            int row = it >> 2;
            int c4  = it & 3;
            float4 v = *(const float4*)(A + (size_t)(m0 + row) * K + k0 + c4 * 4);
            As[c4 * 4 + 0][row] = v.x;
            As[c4 * 4 + 1][row] = v.y;
            As[c4 * 4 + 2][row] = v.z;
            As[c4 * 4 + 3][row] = v.w;
        }
        #pragma unroll
        for (int it = tid; it < BK * BN / 4; it += 256) {
            int row = it / (BN / 4);
            int c4  = it % (BN / 4);
            *(float4*)(&Bs[row][c4 * 4]) =
                *(const float4*)(Bm + (size_t)(k0 + row) * N + n0 + c4 * 4);
        }
        __syncthreads();

        #pragma unroll
        for (int kk = 0; kk < BK; kk++) {
            float a[TM], b[TN];
            #pragma unroll
            for (int i = 0; i < TM; i += 4) {
                float4 v = *(const float4*)&As[kk][tmg * TM + i];
                a[i + 0] = v.x; a[i + 1] = v.y; a[i + 2] = v.z; a[i + 3] = v.w;
            }
            #pragma unroll
            for (int j = 0; j < TN; j += 4) {
                float4 v = *(const float4*)&Bs[kk][tng * TN + j];
                b[j + 0] = v.x; b[j + 1] = v.y; b[j + 2] = v.z; b[j + 3] = v.w;
            }
            #pragma unroll
            for (int i = 0; i < TM; i++)
                #pragma unroll
                for (int j = 0; j < TN; j++)
                    acc[i][j] = fmaf(a[i], b[j], acc[i][j]);
        }
        __syncthreads();
    }

    #pragma unroll
    for (int i = 0; i < TM; i++) {
        int m = m0 + tmg * TM + i;
        float* crow = C + (size_t)m * N + n0 + tng * TN;
        #pragma unroll
        for (int j = 0; j < TN; j += 4) {
            float4 v;
            if (bias) {
                int n = n0 + tng * TN + j;
                v.x = acc[i][j + 0] + bias[n + 0];
                v.y = acc[i][j + 1] + bias[n + 1];
                v.z = acc[i][j + 2] + bias[n + 2];
                v.w = acc[i][j + 3] + bias[n + 3];
            } else {
                v.x = acc[i][j + 0]; v.y = acc[i][j + 1];
                v.z = acc[i][j + 2]; v.w = acc[i][j + 3];
            }
            *(float4*)(crow + j) = v;
        }
    }
}

// ---------------- gather + weighted sum -> y[b,l,h*128+d] -------------------
__global__ void __launch_bounds__(256) gather_kernel(const float* __restrict__ x)
{
    __shared__ float ws  [HH][SS];   // kernel weight per tap
    __shared__ float frs [HH][SS];   // interp fraction per tap
    __shared__ int   i0s [HH][SS];
    __shared__ int   i1s [HH][SS];

    const int bl = blockIdx.x;         // b*L + l
    const int b  = bl >> 10;
    const int l  = bl & (LL - 1);
    const int tid = threadIdx.x;

    {   // phase A: per (h,s) tap parameters — STRICT unfused fp32 (match XLA)
        int h = tid >> 5;
        int s = tid & 31;
        float freq  = g_freq [bl * HH + h];
        float phase = g_phase[bl * HH + h];
        float tap   = (float)(s - 16) + 0.5f;                  // exact
        // offs = phase + freq*tap  -- separate rounded mul and add, NO fma
        float offs  = __fadd_rn(phase, __fmul_rn(freq, tap));
        float pos   = __fadd_rn((float)l, offs);
        pos = fmaxf(pos, 0.0f);
        pos = fminf(pos, (float)(LL - 1));
        float i0f  = floorf(pos);
        float frac = __fsub_rn(pos, i0f);
        int i0 = (int)i0f;
        int i1 = min(i0 + 1, LL - 1);
        // bin = clip(floor((offs + 256)/512 * 64), 0, 63); /512 and *64 exact
        float tb = __fmul_rn(__fadd_rn(offs, 256.0f), 0.125f);
        int bin = (int)floorf(tb);
        bin = max(0, min(bin, KK - 1));
        ws [h][s] = g_kmat[((size_t)bl * HH + h) * KK + bin];
        frs[h][s] = frac;
        i0s[h][s] = i0 * CC;
        i1s[h][s] = i1 * CC;
    }
    __syncthreads();

    const float* xb = x + (size_t)b * (LL * CC);
    #pragma unroll
    for (int r = 0; r < 4; r++) {
        int oi = r * 256 + tid;        // output channel within (b,l)
        int h  = oi >> 7;
        int d  = oi & (DD - 1);
        const float* xhd = xb + h * DD + d;
        float acc = 0.0f;
        #pragma unroll 8
        for (int s = 0; s < SS; s++) {
            float g0 = __ldg(xhd + i0s[h][s]);
            float g1 = __ldg(xhd + i1s[h][s]);
            // gathered = g0 + frac*(g1-g0)  -- unfused, matching reference
            float gathered = __fadd_rn(g0, __fmul_rn(frs[h][s], __fsub_rn(g1, g0)));
            acc = __fmaf_rn(ws[h][s], gathered, acc);
        }
        g_y[(size_t)bl * CC + oi] = acc;
    }
}

// ---------------- launch -----------------------------------------------------
extern "C" void kernel_launch(void* const* d_in, const int* in_sizes, int n_in,
                              void* d_out, int out_size) {
    const float* x        = (const float*)d_in[0];
    const float* wave_w   = (const float*)d_in[1];
    const float* wave_b   = (const float*)d_in[2];
    const float* kernel_w = (const float*)d_in[3];
    const float* kernel_b = (const float*)d_in[4];
    const float* out_w    = (const float*)d_in[5];
    float* out = (float*)d_out;

    float *p_wt_out, *p_wt_ker, *p_kmat, *p_y;
    cudaGetSymbolAddress((void**)&p_wt_out, g_wt_out);
    cudaGetSymbolAddress((void**)&p_wt_ker, g_wt_ker);
    cudaGetSymbolAddress((void**)&p_kmat,   g_kmat);
    cudaGetSymbolAddress((void**)&p_y,      g_y);

    // 1. transpose weights for coalesced GEMM B-operand reads
    transpose_kernel<<<dim3(CC / 32, CC / 32), dim3(32, 8)>>>(out_w, p_wt_out, CC, CC);
    transpose_kernel<<<dim3(CC / 32, HK / 32), dim3(32, 8)>>>(kernel_w, p_wt_ker, HK, CC);

    // 2. wave -> freq/phase (reference-faithful numerics)
    wave_exact_kernel<<<BL / 8, 128>>>(x, wave_w, wave_b);

    // 3. kmat = x @ kernel_w^T + kernel_b   [2048 x 512]
    sgemm_kernel<64, 64, 4, 4><<<dim3(HK / 64, BL / 64), 256>>>(
        x, p_wt_ker, kernel_b, p_kmat, BL, HK, CC);

    // 4. gather + weighted reduce -> y
    gather_kernel<<<BL, 256>>>(x);

    // 5. out = y @ out_w^T                   [2048 x 1024]
    sgemm_kernel<128, 64, 8, 4><<<dim3(CC / 64, BL / 128), 256>>>(
        p_y, p_wt_out, nullptr, out, BL, CC, CC);

    (void)in_sizes; (void)n_in; (void)out_size;
}

// round 4
// speedup vs baseline: 1.4805x; 1.4805x over previous
#include <cuda_runtime.h>
#include <math.h>
#include <stdint.h>

// Problem constants (fixed by setup_inputs)
namespace {
constexpr int BB = 2;
constexpr int LL = 1024;
constexpr int CC = 1024;
constexpr int HH = 8;
constexpr int DD = 128;   // CC / HH
constexpr int SS = 32;    // sample taps
constexpr int KK = 64;    // kernel taps
constexpr int BL = BB * LL;           // 2048
constexpr int HK = HH * KK;           // 512
}

// ---------------- scratch (static device globals; no runtime allocation) ----
__device__ float g_freq [BL * HH];        // [B*L, H]
__device__ float g_phase[BL * HH];        // [B*L, H]
__device__ float g_kmat [BL * HK];        // [B*L, H*K]  (4 MB)
__device__ float g_y    [BL * CC];        // [B*L, C]    (8 MB, tf32-rounded)
__device__ float g_xt   [BL * CC];        // x tf32-rounded (8 MB)
__device__ float g_wk   [HK * CC];        // kernel_w tf32-rounded [N][K] (2 MB)
__device__ float g_wo   [CC * CC];        // out_w tf32-rounded [N][K] (4 MB)

// ---------------- small helpers ----------------------------------------------
__device__ __forceinline__ uint32_t cvt_tf32(float x) {
    uint32_t r; asm("cvt.rna.tf32.f32 %0, %1;" : "=r"(r) : "f"(x)); return r;
}
__device__ __forceinline__ float cvt_tf32f(float x) {
    return __uint_as_float(cvt_tf32(x));
}
__device__ __forceinline__ uint32_t smem_u32(const void* p) {
    return (uint32_t)__cvta_generic_to_shared(p);
}
__device__ __forceinline__ void cp_async16(uint32_t dst, const void* src) {
    asm volatile("cp.async.cg.shared.global [%0], [%1], 16;" :: "r"(dst), "l"(src));
}

// ---------------- elementwise tf32 rounding pass ------------------------------
__global__ void __launch_bounds__(256) cvt_tf32_kernel(
    const float* __restrict__ in, float* __restrict__ out, int n4) {
    int i = blockIdx.x * 256 + threadIdx.x;
    if (i < n4) {
        float4 v = ((const float4*)in)[i];
        v.x = cvt_tf32f(v.x); v.y = cvt_tf32f(v.y);
        v.z = cvt_tf32f(v.z); v.w = cvt_tf32f(v.w);
        ((float4*)out)[i] = v;
    }
}

// ---------------- XLA/Eigen fast-tanh f32 ------------------------------------
__device__ __forceinline__ float tanh_xla(float x) {
    float xc = fminf(fmaxf(x, -7.99881172180175781f), 7.99881172180175781f);
    float x2 = __fmul_rn(xc, xc);
    float p = __fmaf_rn(x2, -2.76076847742355e-16f, 2.00018790482477e-13f);
    p = __fmaf_rn(x2, p, -8.60467152213735e-11f);
    p = __fmaf_rn(x2, p,  5.12229709037114e-08f);
    p = __fmaf_rn(x2, p,  1.48572235717979e-05f);
    p = __fmaf_rn(x2, p,  6.37261928875436e-04f);
    p = __fmaf_rn(x2, p,  4.89352455891786e-03f);
    p = __fmul_rn(xc, p);
    float q = __fmaf_rn(x2, 1.19825839466702e-06f, 1.18534705686654e-04f);
    q = __fmaf_rn(x2, q, 2.26843463243900e-03f);
    q = __fmaf_rn(x2, q, 4.89352518554385e-03f);
    float r = __fdiv_rn(p, q);
    return (fabsf(x) < 0.0004f) ? x : r;
}

// ---------------- wave: sequential-FMA dots -> freq/phase (FROZEN numerics) ---
__global__ void __launch_bounds__(128) wave_exact_kernel(
    const float* __restrict__ x,
    const float* __restrict__ wave_w,   // [16, C]
    const float* __restrict__ wave_b)   // [16] (zeros)
{
    __shared__ float xs[8][CC];
    __shared__ float wv[8][16];
    const int bl0 = blockIdx.x * 8;
    for (int i = threadIdx.x; i < 8 * CC / 4; i += 128) {
        int r = i >> 8;
        int c4 = i & 255;
        ((float4*)xs[r])[c4] = ((const float4*)(x + (size_t)(bl0 + r) * CC))[c4];
    }
    __syncthreads();

    const int rl = threadIdx.x >> 4;
    const int j  = threadIdx.x & 15;
    const float* wr = wave_w + j * CC;
    const float* xr = xs[rl];
    float acc = 0.0f;
    for (int k = 0; k < CC; k++)
        acc = __fmaf_rn(xr[k], __ldg(wr + k), acc);   // serial chain, fixed order
    acc = __fadd_rn(acc, __ldg(wave_b + j));
    wv[rl][j] = acc;
    __syncthreads();

    if (threadIdx.x < 64) {
        int r = threadIdx.x >> 3;
        int h = threadIdx.x & 7;
        float w0 = wv[r][2 * h];
        float w1 = wv[r][2 * h + 1];
        float t0  = tanh_xla(__fmul_rn(0.5f, w0));
        float sig = __fadd_rn(0.5f, __fmul_rn(0.5f, t0));
        float freq = __fadd_rn(1.0f, __fmul_rn(sig, 15.0f));   // STRICT mul,add
        float t1 = tanh_xla(w1);
        float phase = __fmul_rn(t1, freq);
        g_freq [(bl0 + r) * HH + h] = freq;
        g_phase[(bl0 + r) * HH + h] = phase;
    }
}

// ---------------- tf32 tensor-core GEMM ---------------------------------------
// C[M][N] = A[M][K] * B[N][K]^T (+bias[n]).  A, B already tf32-rounded fp32.
// Block 128x128, BK=16, cp.async double-buffered. 8 warps: 4(m) x 2(n),
// warp tile 32x64 via mma.sync.m16n8k8 tf32 (2 m-frags x 8 n-frags).
namespace {
constexpr int GBM = 128, GBN = 128, GBK = 16, GPAD = 20;  // 20-float rows: conflict-free
}
__global__ void __launch_bounds__(256, 1) gemm_tf32_kernel(
    const float* __restrict__ A, const float* __restrict__ Bw,
    const float* __restrict__ bias, float* __restrict__ C,
    int M, int N, int K)
{
    __shared__ float As[2][GBM][GPAD];
    __shared__ float Bs[2][GBN][GPAD];

    const int tid = threadIdx.x;
    const int m0 = blockIdx.y * GBM;
    const int n0 = blockIdx.x * GBN;

    const int lane = tid & 31;
    const int g = lane >> 2;       // group 0..7
    const int t = lane & 3;        // thread-in-group 0..3
    const int wm = (tid >> 5) & 3; // warp m index 0..3
    const int wn = tid >> 7;       // warp n index 0..1
    const int m_off = wm * 32;
    const int n_off = wn * 64;

    // fill mapping: thread -> (row, two 16B chunks)
    const int f_row = tid >> 1;
    const int f_c0  = (tid & 1) * 2;
    const uint32_t as_base = smem_u32(&As[0][0][0]);
    const uint32_t bs_base = smem_u32(&Bs[0][0][0]);

    const int NK = K / GBK;

    auto fill = [&](int buf, int k0) {
        const float* asrc = A  + (size_t)(m0 + f_row) * K + k0;
        const float* bsrc = Bw + (size_t)(n0 + f_row) * K + k0;
        uint32_t ad = as_base + ((buf * GBM + f_row) * GPAD) * 4;
        uint32_t bd = bs_base + ((buf * GBN + f_row) * GPAD) * 4;
        #pragma unroll
        for (int j = 0; j < 2; j++) {
            int ch = f_c0 + j;
            cp_async16(ad + ch * 16, asrc + ch * 4);
            cp_async16(bd + ch * 16, bsrc + ch * 4);
        }
    };

    float c[2][8][4];
    #pragma unroll
    for (int i = 0; i < 2; i++)
        #pragma unroll
        for (int j = 0; j < 8; j++)
            #pragma unroll
            for (int q = 0; q < 4; q++) c[i][j][q] = 0.0f;

    fill(0, 0);
    asm volatile("cp.async.commit_group;");

    for (int it = 0; it < NK; ++it) {
        if (it + 1 < NK) {
            fill((it + 1) & 1, (it + 1) * GBK);
            asm volatile("cp.async.commit_group;");
            asm volatile("cp.async.wait_group 1;");
        } else {
            asm volatile("cp.async.wait_group 0;");
        }
        __syncthreads();

        const int buf = it & 1;
        #pragma unroll
        for (int ks = 0; ks < 2; ks++) {
            const int k8 = ks * 8;
            uint32_t a[2][4], b[8][2];
            #pragma unroll
            for (int mf = 0; mf < 2; mf++) {
                const float* ar = &As[buf][m_off + 16 * mf][0];
                a[mf][0] = __float_as_uint(ar[(g     ) * GPAD + k8 + t    ]);
                a[mf][1] = __float_as_uint(ar[(g + 8 ) * GPAD + k8 + t    ]);
                a[mf][2] = __float_as_uint(ar[(g     ) * GPAD + k8 + t + 4]);
                a[mf][3] = __float_as_uint(ar[(g + 8 ) * GPAD + k8 + t + 4]);
            }
            #pragma unroll
            for (int nf = 0; nf < 8; nf++) {
                const float* br = &Bs[buf][n_off + 8 * nf + g][0];
                b[nf][0] = __float_as_uint(br[k8 + t    ]);
                b[nf][1] = __float_as_uint(br[k8 + t + 4]);
            }
            #pragma unroll
            for (int mf = 0; mf < 2; mf++)
                #pragma unroll
                for (int nf = 0; nf < 8; nf++)
                    asm volatile(
                        "mma.sync.aligned.m16n8k8.row.col.f32.tf32.tf32.f32 "
                        "{%0,%1,%2,%3}, {%4,%5,%6,%7}, {%8,%9}, {%0,%1,%2,%3};"
                        : "+f"(c[mf][nf][0]), "+f"(c[mf][nf][1]),
                          "+f"(c[mf][nf][2]), "+f"(c[mf][nf][3])
                        : "r"(a[mf][0]), "r"(a[mf][1]), "r"(a[mf][2]), "r"(a[mf][3]),
                          "r"(b[nf][0]), "r"(b[nf][1]));
        }
        __syncthreads();
    }

    // epilogue
    #pragma unroll
    for (int nf = 0; nf < 8; nf++) {
        int col = n0 + n_off + 8 * nf + 2 * t;
        float bb0 = 0.0f, bb1 = 0.0f;
        if (bias) { bb0 = __ldg(bias + col); bb1 = __ldg(bias + col + 1); }
        #pragma unroll
        for (int mf = 0; mf < 2; mf++) {
            int row = m0 + m_off + 16 * mf + g;
            float2 v0 = make_float2(c[mf][nf][0] + bb0, c[mf][nf][1] + bb1);
            *(float2*)(C + (size_t)row * N + col) = v0;
            float2 v1 = make_float2(c[mf][nf][2] + bb0, c[mf][nf][3] + bb1);
            *(float2*)(C + (size_t)(row + 8) * N + col) = v1;
        }
    }
}

// ---------------- gather + weighted sum -> y[b,l,c] (tf32-rounded) -----------
__global__ void __launch_bounds__(256) gather_kernel(const float* __restrict__ x)
{
    __shared__ float ws  [HH][SS];
    __shared__ float frs [HH][SS];
    __shared__ int   i0s [HH][SS];
    __shared__ int   i1s [HH][SS];

    const int bl = blockIdx.x;
    const int b  = bl >> 10;
    const int l  = bl & (LL - 1);
    const int tid = threadIdx.x;

    {   // per (h,s) tap parameters — FROZEN strict unfused fp32
        int h = tid >> 5;
        int s = tid & 31;
        float freq  = g_freq [bl * HH + h];
        float phase = g_phase[bl * HH + h];
        float tap   = (float)(s - 16) + 0.5f;
        float offs  = __fadd_rn(phase, __fmul_rn(freq, tap));   // NO fma
        float pos   = __fadd_rn((float)l, offs);
        pos = fmaxf(pos, 0.0f);
        pos = fminf(pos, (float)(LL - 1));
        float i0f  = floorf(pos);
        float frac = __fsub_rn(pos, i0f);
        int i0 = (int)i0f;
        int i1 = min(i0 + 1, LL - 1);
        float tb = __fmul_rn(__fadd_rn(offs, 256.0f), 0.125f);
        int bin = (int)floorf(tb);
        bin = max(0, min(bin, KK - 1));
        ws [h][s] = g_kmat[((size_t)bl * HH + h) * KK + bin];
        frs[h][s] = frac;
        i0s[h][s] = i0 * CC;
        i1s[h][s] = i1 * CC;
    }
    __syncthreads();

    const float* xb = x + (size_t)b * (LL * CC);
    #pragma unroll
    for (int r = 0; r < 4; r++) {
        int oi = r * 256 + tid;
        int h  = oi >> 7;
        int d  = oi & (DD - 1);
        const float* xhd = xb + h * DD + d;
        float acc = 0.0f;
        #pragma unroll 8
        for (int s = 0; s < SS; s++) {
            float g0 = __ldg(xhd + i0s[h][s]);
            float g1 = __ldg(xhd + i1s[h][s]);
            float gathered = __fadd_rn(g0, __fmul_rn(frs[h][s], __fsub_rn(g1, g0)));
            acc = __fmaf_rn(ws[h][s], gathered, acc);
        }
        g_y[(size_t)bl * CC + oi] = cvt_tf32f(acc);  // pre-round for tf32 GEMM
    }
}

// ---------------- launch -----------------------------------------------------
extern "C" void kernel_launch(void* const* d_in, const int* in_sizes, int n_in,
                              void* d_out, int out_size) {
    const float* x        = (const float*)d_in[0];
    const float* wave_w   = (const float*)d_in[1];
    const float* wave_b   = (const float*)d_in[2];
    const float* kernel_w = (const float*)d_in[3];
    const float* kernel_b = (const float*)d_in[4];
    const float* out_w    = (const float*)d_in[5];
    float* out = (float*)d_out;

    float *p_kmat, *p_y, *p_xt, *p_wk, *p_wo;
    cudaGetSymbolAddress((void**)&p_kmat, g_kmat);
    cudaGetSymbolAddress((void**)&p_y,    g_y);
    cudaGetSymbolAddress((void**)&p_xt,   g_xt);
    cudaGetSymbolAddress((void**)&p_wk,   g_wk);
    cudaGetSymbolAddress((void**)&p_wo,   g_wo);

    // 1. tf32 rounding passes (x, kernel_w, out_w) — no transposes needed
    cvt_tf32_kernel<<<(BL * CC / 4 + 255) / 256, 256>>>(x,        p_xt, BL * CC / 4);
    cvt_tf32_kernel<<<(HK * CC / 4 + 255) / 256, 256>>>(kernel_w, p_wk, HK * CC / 4);
    cvt_tf32_kernel<<<(CC * CC / 4 + 255) / 256, 256>>>(out_w,    p_wo, CC * CC / 4);

    // 2. wave -> freq/phase (exact fp32; feeds the discontinuous bin path)
    wave_exact_kernel<<<BL / 8, 128>>>(x, wave_w, wave_b);

    // 3. kmat = x @ kernel_w^T + kernel_b   [2048 x 512] (tf32 tensor cores)
    gemm_tf32_kernel<<<dim3(HK / GBN, BL / GBM), 256>>>(
        p_xt, p_wk, kernel_b, p_kmat, BL, HK, CC);

    // 4. gather + weighted reduce -> y (tf32-rounded)
    gather_kernel<<<BL, 256>>>(x);

    // 5. out = y @ out_w^T                   [2048 x 1024] (tf32 tensor cores)
    gemm_tf32_kernel<<<dim3(CC / GBN, BL / GBM), 256>>>(
        p_y, p_wo, nullptr, out, BL, CC, CC);

    (void)in_sizes; (void)n_in; (void)out_size;
}

// round 5
// speedup vs baseline: 2.1137x; 1.4276x over previous
#include <cuda_runtime.h>
#include <math.h>
#include <stdint.h>

// Problem constants (fixed by setup_inputs)
namespace {
constexpr int BB = 2;
constexpr int LL = 1024;
constexpr int CC = 1024;
constexpr int HH = 8;
constexpr int DD = 128;   // CC / HH
constexpr int SS = 32;    // sample taps
constexpr int KK = 64;    // kernel taps
constexpr int BL = BB * LL;           // 2048
constexpr int HK = HH * KK;           // 512
constexpr int WPITCH = 1028;          // wave_w smem pitch (conflict-free float4)
}

// ---------------- scratch (static device globals; no runtime allocation) ----
__device__ float g_freq [BL * HH];        // [B*L, H]
__device__ float g_phase[BL * HH];        // [B*L, H]
__device__ float g_kmat [BL * HK];        // [B*L, H*K]  (4 MB)
__device__ float g_y    [BL * CC];        // [B*L, C]    (8 MB, tf32-rounded)
__device__ float g_xt   [BL * CC];        // x tf32-rounded (8 MB)
__device__ float g_wk   [HK * CC];        // kernel_w tf32-rounded [N][K] (2 MB)
__device__ float g_wo   [CC * CC];        // out_w tf32-rounded [N][K] (4 MB)

// ---------------- small helpers ----------------------------------------------
__device__ __forceinline__ uint32_t cvt_tf32(float x) {
    uint32_t r; asm("cvt.rna.tf32.f32 %0, %1;" : "=r"(r) : "f"(x)); return r;
}
__device__ __forceinline__ float cvt_tf32f(float x) {
    return __uint_as_float(cvt_tf32(x));
}
__device__ __forceinline__ uint32_t smem_u32(const void* p) {
    return (uint32_t)__cvta_generic_to_shared(p);
}
__device__ __forceinline__ void cp_async16(uint32_t dst, const void* src) {
    asm volatile("cp.async.cg.shared.global [%0], [%1], 16;" :: "r"(dst), "l"(src));
}

// ---------------- elementwise tf32 rounding pass ------------------------------
__global__ void __launch_bounds__(256) cvt_tf32_kernel(
    const float* __restrict__ in, float* __restrict__ out, int n4) {
    int i = blockIdx.x * 256 + threadIdx.x;
    if (i < n4) {
        float4 v = ((const float4*)in)[i];
        v.x = cvt_tf32f(v.x); v.y = cvt_tf32f(v.y);
        v.z = cvt_tf32f(v.z); v.w = cvt_tf32f(v.w);
        ((float4*)out)[i] = v;
    }
}

// ---------------- XLA/Eigen fast-tanh f32 ------------------------------------
__device__ __forceinline__ float tanh_xla(float x) {
    float xc = fminf(fmaxf(x, -7.99881172180175781f), 7.99881172180175781f);
    float x2 = __fmul_rn(xc, xc);
    float p = __fmaf_rn(x2, -2.76076847742355e-16f, 2.00018790482477e-13f);
    p = __fmaf_rn(x2, p, -8.60467152213735e-11f);
    p = __fmaf_rn(x2, p,  5.12229709037114e-08f);
    p = __fmaf_rn(x2, p,  1.48572235717979e-05f);
    p = __fmaf_rn(x2, p,  6.37261928875436e-04f);
    p = __fmaf_rn(x2, p,  4.89352455891786e-03f);
    p = __fmul_rn(xc, p);
    float q = __fmaf_rn(x2, 1.19825839466702e-06f, 1.18534705686654e-04f);
    q = __fmaf_rn(x2, q, 2.26843463243900e-03f);
    q = __fmaf_rn(x2, q, 4.89352518554385e-03f);
    float r = __fdiv_rn(p, q);
    return (fabsf(x) < 0.0004f) ? x : r;
}

// ---------------- wave: serial-FMA dots -> freq/phase (FROZEN numerics) ------
// Bit-identical k=0..1023 sequential __fmaf_rn chain per output. Restructured
// for speed only: wave_w staged in padded shared, float4 loads, 2 independent
// chains per thread for FMA-pipe ILP. 16 positions per block, 128 blocks.
__global__ void __launch_bounds__(128) wave_exact_kernel(
    const float* __restrict__ x,
    const float* __restrict__ wave_w,   // [16, C]
    const float* __restrict__ wave_b)   // [16] (zeros)
{
    extern __shared__ float sm[];
    float* xs  = sm;                 // [16][1024] = x rows (linear copy)
    float* wsm = sm + 16 * CC;       // [16][WPITCH] padded wave_w
    __shared__ float wvs[16][16];

    const int bl0 = blockIdx.x * 16;
    const int tid = threadIdx.x;

    // stage x rows (contiguous) and wave_w (padded pitch)
    const float4* xg = (const float4*)(x + (size_t)bl0 * CC);
    #pragma unroll
    for (int i = tid; i < 16 * (CC / 4); i += 128)
        ((float4*)xs)[i] = xg[i];
    const float4* wg = (const float4*)wave_w;
    #pragma unroll
    for (int i = tid; i < 16 * (CC / 4); i += 128) {
        int r = i >> 8;             // CC/4 = 256
        int c = i & 255;
        *(float4*)(wsm + r * WPITCH + c * 4) = wg[i];
    }
    __syncthreads();

    // two serial chains per thread: rows rl and rl+8, output j
    const int j  = tid & 15;
    const int rl = tid >> 4;        // 0..7
    const float4* wr = (const float4*)(wsm + j * WPITCH);
    const float4* x0 = (const float4*)(xs + rl * CC);
    const float4* x1 = (const float4*)(xs + (rl + 8) * CC);
    float a0 = 0.0f, a1 = 0.0f;
    #pragma unroll 4
    for (int k4 = 0; k4 < CC / 4; k4++) {
        float4 wv = wr[k4];
        float4 v0 = x0[k4];
        float4 v1 = x1[k4];
        a0 = __fmaf_rn(v0.x, wv.x, a0);  a1 = __fmaf_rn(v1.x, wv.x, a1);
        a0 = __fmaf_rn(v0.y, wv.y, a0);  a1 = __fmaf_rn(v1.y, wv.y, a1);
        a0 = __fmaf_rn(v0.z, wv.z, a0);  a1 = __fmaf_rn(v1.z, wv.z, a1);
        a0 = __fmaf_rn(v0.w, wv.w, a0);  a1 = __fmaf_rn(v1.w, wv.w, a1);
    }
    wvs[rl    ][j] = __fadd_rn(a0, __ldg(wave_b + j));
    wvs[rl + 8][j] = __fadd_rn(a1, __ldg(wave_b + j));
    __syncthreads();

    {   // elementwise tail: 16 rows x 8 heads = 128 threads
        int r = tid >> 3;
        int h = tid & 7;
        float w0 = wvs[r][2 * h];
        float w1 = wvs[r][2 * h + 1];
        float t0  = tanh_xla(__fmul_rn(0.5f, w0));
        float sig = __fadd_rn(0.5f, __fmul_rn(0.5f, t0));
        float freq = __fadd_rn(1.0f, __fmul_rn(sig, 15.0f));   // STRICT mul,add
        float t1 = tanh_xla(w1);
        float phase = __fmul_rn(t1, freq);
        g_freq [(bl0 + r) * HH + h] = freq;
        g_phase[(bl0 + r) * HH + h] = phase;
    }
}

// ---------------- tf32 tensor-core GEMM ---------------------------------------
// C[M][N] = A[M][K] * B[N][K]^T (+bias[n]).  A, B already tf32-rounded fp32.
namespace {
constexpr int GBM = 128, GBN = 128, GBK = 16, GPAD = 20;
}
__global__ void __launch_bounds__(256, 1) gemm_tf32_kernel(
    const float* __restrict__ A, const float* __restrict__ Bw,
    const float* __restrict__ bias, float* __restrict__ C,
    int M, int N, int K)
{
    __shared__ float As[2][GBM][GPAD];
    __shared__ float Bs[2][GBN][GPAD];

    const int tid = threadIdx.x;
    const int m0 = blockIdx.y * GBM;
    const int n0 = blockIdx.x * GBN;

    const int lane = tid & 31;
    const int g = lane >> 2;
    const int t = lane & 3;
    const int wm = (tid >> 5) & 3;
    const int wn = tid >> 7;
    const int m_off = wm * 32;
    const int n_off = wn * 64;

    const int f_row = tid >> 1;
    const int f_c0  = (tid & 1) * 2;
    const uint32_t as_base = smem_u32(&As[0][0][0]);
    const uint32_t bs_base = smem_u32(&Bs[0][0][0]);

    const int NK = K / GBK;

    auto fill = [&](int buf, int k0) {
        const float* asrc = A  + (size_t)(m0 + f_row) * K + k0;
        const float* bsrc = Bw + (size_t)(n0 + f_row) * K + k0;
        uint32_t ad = as_base + ((buf * GBM + f_row) * GPAD) * 4;
        uint32_t bd = bs_base + ((buf * GBN + f_row) * GPAD) * 4;
        #pragma unroll
        for (int jj = 0; jj < 2; jj++) {
            int ch = f_c0 + jj;
            cp_async16(ad + ch * 16, asrc + ch * 4);
            cp_async16(bd + ch * 16, bsrc + ch * 4);
        }
    };

    float c[2][8][4];
    #pragma unroll
    for (int i = 0; i < 2; i++)
        #pragma unroll
        for (int jj = 0; jj < 8; jj++)
            #pragma unroll
            for (int q = 0; q < 4; q++) c[i][jj][q] = 0.0f;

    fill(0, 0);
    asm volatile("cp.async.commit_group;");

    for (int it = 0; it < NK; ++it) {
        if (it + 1 < NK) {
            fill((it + 1) & 1, (it + 1) * GBK);
            asm volatile("cp.async.commit_group;");
            asm volatile("cp.async.wait_group 1;");
        } else {
            asm volatile("cp.async.wait_group 0;");
        }
        __syncthreads();

        const int buf = it & 1;
        #pragma unroll
        for (int ks = 0; ks < 2; ks++) {
            const int k8 = ks * 8;
            uint32_t a[2][4], b[8][2];
            #pragma unroll
            for (int mf = 0; mf < 2; mf++) {
                const float* ar = &As[buf][m_off + 16 * mf][0];
                a[mf][0] = __float_as_uint(ar[(g     ) * GPAD + k8 + t    ]);
                a[mf][1] = __float_as_uint(ar[(g + 8 ) * GPAD + k8 + t    ]);
                a[mf][2] = __float_as_uint(ar[(g     ) * GPAD + k8 + t + 4]);
                a[mf][3] = __float_as_uint(ar[(g + 8 ) * GPAD + k8 + t + 4]);
            }
            #pragma unroll
            for (int nf = 0; nf < 8; nf++) {
                const float* br = &Bs[buf][n_off + 8 * nf + g][0];
                b[nf][0] = __float_as_uint(br[k8 + t    ]);
                b[nf][1] = __float_as_uint(br[k8 + t + 4]);
            }
            #pragma unroll
            for (int mf = 0; mf < 2; mf++)
                #pragma unroll
                for (int nf = 0; nf < 8; nf++)
                    asm volatile(
                        "mma.sync.aligned.m16n8k8.row.col.f32.tf32.tf32.f32 "
                        "{%0,%1,%2,%3}, {%4,%5,%6,%7}, {%8,%9}, {%0,%1,%2,%3};"
                        : "+f"(c[mf][nf][0]), "+f"(c[mf][nf][1]),
                          "+f"(c[mf][nf][2]), "+f"(c[mf][nf][3])
                        : "r"(a[mf][0]), "r"(a[mf][1]), "r"(a[mf][2]), "r"(a[mf][3]),
                          "r"(b[nf][0]), "r"(b[nf][1]));
        }
        __syncthreads();
    }

    #pragma unroll
    for (int nf = 0; nf < 8; nf++) {
        int col = n0 + n_off + 8 * nf + 2 * t;
        float bb0 = 0.0f, bb1 = 0.0f;
        if (bias) { bb0 = __ldg(bias + col); bb1 = __ldg(bias + col + 1); }
        #pragma unroll
        for (int mf = 0; mf < 2; mf++) {
            int row = m0 + m_off + 16 * mf + g;
            float2 v0 = make_float2(c[mf][nf][0] + bb0, c[mf][nf][1] + bb1);
            *(float2*)(C + (size_t)row * N + col) = v0;
            float2 v1 = make_float2(c[mf][nf][2] + bb0, c[mf][nf][3] + bb1);
            *(float2*)(C + (size_t)(row + 8) * N + col) = v1;
        }
    }
}

// ---------------- gather + weighted sum -> y[b,l,c] (tf32-rounded) -----------
__global__ void __launch_bounds__(256) gather_kernel(const float* __restrict__ x)
{
    __shared__ float ws  [HH][SS];
    __shared__ float frs [HH][SS];
    __shared__ int   i0s [HH][SS];
    __shared__ int   i1s [HH][SS];

    const int bl = blockIdx.x;
    const int b  = bl >> 10;
    const int l  = bl & (LL - 1);
    const int tid = threadIdx.x;

    {   // per (h,s) tap parameters — FROZEN strict unfused fp32
        int h = tid >> 5;
        int s = tid & 31;
        float freq  = g_freq [bl * HH + h];
        float phase = g_phase[bl * HH + h];
        float tap   = (float)(s - 16) + 0.5f;
        float offs  = __fadd_rn(phase, __fmul_rn(freq, tap));   // NO fma
        float pos   = __fadd_rn((float)l, offs);
        pos = fmaxf(pos, 0.0f);
        pos = fminf(pos, (float)(LL - 1));
        float i0f  = floorf(pos);
        float frac = __fsub_rn(pos, i0f);
        int i0 = (int)i0f;
        int i1 = min(i0 + 1, LL - 1);
        float tb = __fmul_rn(__fadd_rn(offs, 256.0f), 0.125f);
        int bin = (int)floorf(tb);
        bin = max(0, min(bin, KK - 1));
        ws [h][s] = g_kmat[((size_t)bl * HH + h) * KK + bin];
        frs[h][s] = frac;
        i0s[h][s] = i0 * CC;
        i1s[h][s] = i1 * CC;
    }
    __syncthreads();

    const float* xb = x + (size_t)b * (LL * CC);
    #pragma unroll
    for (int r = 0; r < 4; r++) {
        int oi = r * 256 + tid;
        int h  = oi >> 7;
        int d  = oi & (DD - 1);
        const float* xhd = xb + h * DD + d;
        float acc = 0.0f;
        #pragma unroll 8
        for (int s = 0; s < SS; s++) {
            float g0 = __ldg(xhd + i0s[h][s]);
            float g1 = __ldg(xhd + i1s[h][s]);
            float gathered = __fadd_rn(g0, __fmul_rn(frs[h][s], __fsub_rn(g1, g0)));
            acc = __fmaf_rn(ws[h][s], gathered, acc);
        }
        g_y[(size_t)bl * CC + oi] = cvt_tf32f(acc);  // pre-round for tf32 GEMM
    }
}

// ---------------- launch -----------------------------------------------------
extern "C" void kernel_launch(void* const* d_in, const int* in_sizes, int n_in,
                              void* d_out, int out_size) {
    const float* x        = (const float*)d_in[0];
    const float* wave_w   = (const float*)d_in[1];
    const float* wave_b   = (const float*)d_in[2];
    const float* kernel_w = (const float*)d_in[3];
    const float* kernel_b = (const float*)d_in[4];
    const float* out_w    = (const float*)d_in[5];
    float* out = (float*)d_out;

    float *p_kmat, *p_y, *p_xt, *p_wk, *p_wo;
    cudaGetSymbolAddress((void**)&p_kmat, g_kmat);
    cudaGetSymbolAddress((void**)&p_y,    g_y);
    cudaGetSymbolAddress((void**)&p_xt,   g_xt);
    cudaGetSymbolAddress((void**)&p_wk,   g_wk);
    cudaGetSymbolAddress((void**)&p_wo,   g_wo);

    // 1. tf32 rounding passes (x, kernel_w, out_w)
    cvt_tf32_kernel<<<(BL * CC / 4 + 255) / 256, 256>>>(x,        p_xt, BL * CC / 4);
    cvt_tf32_kernel<<<(HK * CC / 4 + 255) / 256, 256>>>(kernel_w, p_wk, HK * CC / 4);
    cvt_tf32_kernel<<<(CC * CC / 4 + 255) / 256, 256>>>(out_w,    p_wo, CC * CC / 4);

    // 2. wave -> freq/phase (exact fp32 chain; smem-staged)
    constexpr int WAVE_SMEM = (16 * CC + 16 * WPITCH) * 4;   // ~129.5 KB
    cudaFuncSetAttribute(wave_exact_kernel,
                         cudaFuncAttributeMaxDynamicSharedMemorySize, WAVE_SMEM);
    wave_exact_kernel<<<BL / 16, 128, WAVE_SMEM>>>(x, wave_w, wave_b);

    // 3. kmat = x @ kernel_w^T + kernel_b   [2048 x 512] (tf32 tensor cores)
    gemm_tf32_kernel<<<dim3(HK / GBN, BL / GBM), 256>>>(
        p_xt, p_wk, kernel_b, p_kmat, BL, HK, CC);

    // 4. gather + weighted reduce -> y (tf32-rounded)
    gather_kernel<<<BL, 256>>>(x);

    // 5. out = y @ out_w^T                   [2048 x 1024] (tf32 tensor cores)
    gemm_tf32_kernel<<<dim3(CC / GBN, BL / GBM), 256>>>(
        p_y, p_wo, nullptr, out, BL, CC, CC);

    (void)in_sizes; (void)n_in; (void)out_size;
}

// round 6
// speedup vs baseline: 2.5220x; 1.1932x over previous
#include <cuda_runtime.h>
#include <cuda_fp16.h>
#include <math.h>
#include <stdint.h>

// Problem constants (fixed by setup_inputs)
namespace {
constexpr int BB = 2;
constexpr int LL = 1024;
constexpr int CC = 1024;
constexpr int HH = 8;
constexpr int DD = 128;   // CC / HH
constexpr int SS = 32;    // sample taps
constexpr int KK = 64;    // kernel taps
constexpr int BL = BB * LL;           // 2048
constexpr int HK = HH * KK;           // 512
constexpr int WPITCH = 1028;          // wave_w smem pitch
}

// ---------------- scratch (static device globals; no runtime allocation) ----
__device__ float  g_freq [BL * HH];
__device__ float  g_phase[BL * HH];
__device__ float  g_kmat [BL * HK];       // 4 MB
__device__ float  g_y    [BL * CC];       // 8 MB (tf32-rounded)
__device__ float  g_xt   [BL * CC];       // x tf32-rounded (8 MB)
__device__ __half g_xh   [BL * CC];       // x fp16 (4 MB) for gather
__device__ float  g_wk   [HK * CC];       // kernel_w tf32 [N][K]
__device__ float  g_wo   [CC * CC];       // out_w tf32 [N][K]

// ---------------- small helpers ----------------------------------------------
__device__ __forceinline__ uint32_t cvt_tf32(float x) {
    uint32_t r; asm("cvt.rna.tf32.f32 %0, %1;" : "=r"(r) : "f"(x)); return r;
}
__device__ __forceinline__ float cvt_tf32f(float x) {
    return __uint_as_float(cvt_tf32(x));
}
__device__ __forceinline__ uint32_t smem_u32(const void* p) {
    return (uint32_t)__cvta_generic_to_shared(p);
}
__device__ __forceinline__ void cp_async16(uint32_t dst, const void* src) {
    asm volatile("cp.async.cg.shared.global [%0], [%1], 16;" :: "r"(dst), "l"(src));
}

// ---------------- converts -----------------------------------------------------
// x: one read -> tf32 copy (GEMM A) + fp16 copy (gather)
__global__ void __launch_bounds__(256) cvt_x_kernel(
    const float* __restrict__ in, float* __restrict__ o32,
    __half2* __restrict__ o16, int n4) {
    int i = blockIdx.x * 256 + threadIdx.x;
    if (i < n4) {
        float4 v = ((const float4*)in)[i];
        float4 t;
        t.x = cvt_tf32f(v.x); t.y = cvt_tf32f(v.y);
        t.z = cvt_tf32f(v.z); t.w = cvt_tf32f(v.w);
        ((float4*)o32)[i] = t;
        o16[2 * i    ] = __floats2half2_rn(v.x, v.y);
        o16[2 * i + 1] = __floats2half2_rn(v.z, v.w);
    }
}
__global__ void __launch_bounds__(256) cvt_tf32_kernel(
    const float* __restrict__ in, float* __restrict__ out, int n4) {
    int i = blockIdx.x * 256 + threadIdx.x;
    if (i < n4) {
        float4 v = ((const float4*)in)[i];
        v.x = cvt_tf32f(v.x); v.y = cvt_tf32f(v.y);
        v.z = cvt_tf32f(v.z); v.w = cvt_tf32f(v.w);
        ((float4*)out)[i] = v;
    }
}

// ---------------- XLA/Eigen fast-tanh f32 ------------------------------------
__device__ __forceinline__ float tanh_xla(float x) {
    float xc = fminf(fmaxf(x, -7.99881172180175781f), 7.99881172180175781f);
    float x2 = __fmul_rn(xc, xc);
    float p = __fmaf_rn(x2, -2.76076847742355e-16f, 2.00018790482477e-13f);
    p = __fmaf_rn(x2, p, -8.60467152213735e-11f);
    p = __fmaf_rn(x2, p,  5.12229709037114e-08f);
    p = __fmaf_rn(x2, p,  1.48572235717979e-05f);
    p = __fmaf_rn(x2, p,  6.37261928875436e-04f);
    p = __fmaf_rn(x2, p,  4.89352455891786e-03f);
    p = __fmul_rn(xc, p);
    float q = __fmaf_rn(x2, 1.19825839466702e-06f, 1.18534705686654e-04f);
    q = __fmaf_rn(x2, q, 2.26843463243900e-03f);
    q = __fmaf_rn(x2, q, 4.89352518554385e-03f);
    float r = __fdiv_rn(p, q);
    return (fabsf(x) < 0.0004f) ? x : r;
}

// ---------------- wave: serial-FMA dots -> freq/phase (FROZEN numerics) ------
// One chain per thread (16 rows x 16 outputs = 256 threads). wave_w staged in
// padded smem; x read directly via __ldg float4 (16 lanes/row -> broadcast).
// Chain order k=0..1023 sequential __fmaf_rn: bit-identical to prior rounds.
__global__ void __launch_bounds__(256) wave_exact_kernel(
    const float* __restrict__ x,
    const float* __restrict__ wave_w,   // [16, C]
    const float* __restrict__ wave_b)   // [16] (zeros)
{
    extern __shared__ float wsm[];      // [16][WPITCH]
    __shared__ float wvs[16][16];

    const int bl0 = blockIdx.x * 16;
    const int tid = threadIdx.x;

    const float4* wg = (const float4*)wave_w;
    #pragma unroll
    for (int i = tid; i < 16 * (CC / 4); i += 256) {
        int r = i >> 8;
        int c = i & 255;
        *(float4*)(wsm + r * WPITCH + c * 4) = wg[i];
    }
    __syncthreads();

    const int j = tid & 15;             // output index
    const int r = tid >> 4;             // local row 0..15
    const float4* wr = (const float4*)(wsm + j * WPITCH);
    const float4* xr = (const float4*)(x + (size_t)(bl0 + r) * CC);
    float a0 = 0.0f;
    #pragma unroll 8
    for (int k4 = 0; k4 < CC / 4; k4++) {
        float4 wv = wr[k4];
        float4 xv = __ldg(xr + k4);
        a0 = __fmaf_rn(xv.x, wv.x, a0);
        a0 = __fmaf_rn(xv.y, wv.y, a0);
        a0 = __fmaf_rn(xv.z, wv.z, a0);
        a0 = __fmaf_rn(xv.w, wv.w, a0);
    }
    wvs[r][j] = __fadd_rn(a0, __ldg(wave_b + j));
    __syncthreads();

    if (tid < 128) {                    // elementwise tail: 16 rows x 8 heads
        int rr = tid >> 3;
        int h  = tid & 7;
        float w0 = wvs[rr][2 * h];
        float w1 = wvs[rr][2 * h + 1];
        float t0  = tanh_xla(__fmul_rn(0.5f, w0));
        float sig = __fadd_rn(0.5f, __fmul_rn(0.5f, t0));
        float freq = __fadd_rn(1.0f, __fmul_rn(sig, 15.0f));   // STRICT mul,add
        float t1 = tanh_xla(w1);
        float phase = __fmul_rn(t1, freq);
        g_freq [(bl0 + rr) * HH + h] = freq;
        g_phase[(bl0 + rr) * HH + h] = phase;
    }
}

// ---------------- tf32 tensor-core GEMM (templated tiles) ---------------------
// C[M][N] = A[M][K] * B[N][K]^T (+bias[n]). 256 threads = WM x WN warps.
namespace { constexpr int GBK = 16, GPAD = 20; }

template <int BM, int BN, int WM, int WN>
__global__ void __launch_bounds__(256, 1) gemm_tf32_kernel(
    const float* __restrict__ A, const float* __restrict__ Bw,
    const float* __restrict__ bias, float* __restrict__ C,
    int M, int N, int K)
{
    constexpr int WTM = BM / WM;           // warp tile m
    constexpr int WTN = BN / WN;           // warp tile n
    constexpr int MF = WTM / 16;
    constexpr int NF = WTN / 8;
    static_assert(WM * WN == 8, "8 warps");

    __shared__ float As[2][BM][GPAD];
    __shared__ float Bs[2][BN][GPAD];

    const int tid = threadIdx.x;
    const int m0 = blockIdx.y * BM;
    const int n0 = blockIdx.x * BN;

    const int lane = tid & 31;
    const int g = lane >> 2;
    const int t = lane & 3;
    const int warp = tid >> 5;
    const int m_off = (warp % WM) * WTM;
    const int n_off = (warp / WM) * WTN;

    const uint32_t as_base = smem_u32(&As[0][0][0]);
    const uint32_t bs_base = smem_u32(&Bs[0][0][0]);
    const int NK = K / GBK;

    auto fill = [&](int buf, int k0) {
        #pragma unroll
        for (int i = tid; i < BM * 4; i += 256) {
            int row = i >> 2, ch = i & 3;
            cp_async16(as_base + ((buf * BM + row) * GPAD) * 4 + ch * 16,
                       A + (size_t)(m0 + row) * K + k0 + ch * 4);
        }
        #pragma unroll
        for (int i = tid; i < BN * 4; i += 256) {
            int row = i >> 2, ch = i & 3;
            cp_async16(bs_base + ((buf * BN + row) * GPAD) * 4 + ch * 16,
                       Bw + (size_t)(n0 + row) * K + k0 + ch * 4);
        }
    };

    float c[MF][NF][4];
    #pragma unroll
    for (int i = 0; i < MF; i++)
        #pragma unroll
        for (int jj = 0; jj < NF; jj++)
            #pragma unroll
            for (int q = 0; q < 4; q++) c[i][jj][q] = 0.0f;

    fill(0, 0);
    asm volatile("cp.async.commit_group;");

    for (int it = 0; it < NK; ++it) {
        if (it + 1 < NK) {
            fill((it + 1) & 1, (it + 1) * GBK);
            asm volatile("cp.async.commit_group;");
            asm volatile("cp.async.wait_group 1;");
        } else {
            asm volatile("cp.async.wait_group 0;");
        }
        __syncthreads();

        const int buf = it & 1;
        #pragma unroll
        for (int ks = 0; ks < 2; ks++) {
            const int k8 = ks * 8;
            uint32_t a[MF][4], b[NF][2];
            #pragma unroll
            for (int mf = 0; mf < MF; mf++) {
                const float* ar = &As[buf][m_off + 16 * mf][0];
                a[mf][0] = __float_as_uint(ar[(g     ) * GPAD + k8 + t    ]);
                a[mf][1] = __float_as_uint(ar[(g + 8 ) * GPAD + k8 + t    ]);
                a[mf][2] = __float_as_uint(ar[(g     ) * GPAD + k8 + t + 4]);
                a[mf][3] = __float_as_uint(ar[(g + 8 ) * GPAD + k8 + t + 4]);
            }
            #pragma unroll
            for (int nf = 0; nf < NF; nf++) {
                const float* br = &Bs[buf][n_off + 8 * nf + g][0];
                b[nf][0] = __float_as_uint(br[k8 + t    ]);
                b[nf][1] = __float_as_uint(br[k8 + t + 4]);
            }
            #pragma unroll
            for (int mf = 0; mf < MF; mf++)
                #pragma unroll
                for (int nf = 0; nf < NF; nf++)
                    asm volatile(
                        "mma.sync.aligned.m16n8k8.row.col.f32.tf32.tf32.f32 "
                        "{%0,%1,%2,%3}, {%4,%5,%6,%7}, {%8,%9}, {%0,%1,%2,%3};"
                        : "+f"(c[mf][nf][0]), "+f"(c[mf][nf][1]),
                          "+f"(c[mf][nf][2]), "+f"(c[mf][nf][3])
                        : "r"(a[mf][0]), "r"(a[mf][1]), "r"(a[mf][2]), "r"(a[mf][3]),
                          "r"(b[nf][0]), "r"(b[nf][1]));
        }
        __syncthreads();
    }

    #pragma unroll
    for (int nf = 0; nf < NF; nf++) {
        int col = n0 + n_off + 8 * nf + 2 * t;
        float bb0 = 0.0f, bb1 = 0.0f;
        if (bias) { bb0 = __ldg(bias + col); bb1 = __ldg(bias + col + 1); }
        #pragma unroll
        for (int mf = 0; mf < MF; mf++) {
            int row = m0 + m_off + 16 * mf + g;
            float2 v0 = make_float2(c[mf][nf][0] + bb0, c[mf][nf][1] + bb1);
            *(float2*)(C + (size_t)row * N + col) = v0;
            float2 v1 = make_float2(c[mf][nf][2] + bb0, c[mf][nf][3] + bb1);
            *(float2*)(C + (size_t)(row + 8) * N + col) = v1;
        }
    }
}

// ---------------- gather + weighted sum (fp16 x values, fp32 math) -----------
__global__ void __launch_bounds__(256) gather_kernel(const __half2* __restrict__ xh2)
{
    __shared__ float ws  [HH][SS];
    __shared__ float frs [HH][SS];
    __shared__ int   i0s [HH][SS];   // row offsets in half2 units (i*CC/2)
    __shared__ int   i1s [HH][SS];

    const int bl = blockIdx.x;
    const int b  = bl >> 10;
    const int l  = bl & (LL - 1);
    const int tid = threadIdx.x;

    {   // per (h,s) tap parameters — FROZEN strict unfused fp32
        int h = tid >> 5;
        int s = tid & 31;
        float freq  = g_freq [bl * HH + h];
        float phase = g_phase[bl * HH + h];
        float tap   = (float)(s - 16) + 0.5f;
        float offs  = __fadd_rn(phase, __fmul_rn(freq, tap));   // NO fma
        float pos   = __fadd_rn((float)l, offs);
        pos = fmaxf(pos, 0.0f);
        pos = fminf(pos, (float)(LL - 1));
        float i0f  = floorf(pos);
        float frac = __fsub_rn(pos, i0f);
        int i0 = (int)i0f;
        int i1 = min(i0 + 1, LL - 1);
        float tb = __fmul_rn(__fadd_rn(offs, 256.0f), 0.125f);
        int bin = (int)floorf(tb);
        bin = max(0, min(bin, KK - 1));
        ws [h][s] = g_kmat[((size_t)bl * HH + h) * KK + bin];
        frs[h][s] = frac;
        i0s[h][s] = i0 * (CC / 2);
        i1s[h][s] = i1 * (CC / 2);
    }
    __syncthreads();

    const __half2* xb = xh2 + (size_t)b * (LL * CC / 2);
    #pragma unroll
    for (int r = 0; r < 2; r++) {
        int oi2 = r * 256 + tid;           // half2 channel index 0..511
        int h   = oi2 >> 6;                // 64 half2 per head
        int d2  = oi2 & 63;
        const __half2* base = xb + h * (DD / 2) + d2;
        float acc0 = 0.0f, acc1 = 0.0f;
        #pragma unroll 8
        for (int s = 0; s < SS; s++) {
            float2 f0 = __half22float2(__ldg(base + i0s[h][s]));
            float2 f1 = __half22float2(__ldg(base + i1s[h][s]));
            float fr = frs[h][s];
            float w  = ws [h][s];
            float ga = __fadd_rn(f0.x, __fmul_rn(fr, __fsub_rn(f1.x, f0.x)));
            float gb = __fadd_rn(f0.y, __fmul_rn(fr, __fsub_rn(f1.y, f0.y)));
            acc0 = __fmaf_rn(w, ga, acc0);
            acc1 = __fmaf_rn(w, gb, acc1);
        }
        float2 o = make_float2(cvt_tf32f(acc0), cvt_tf32f(acc1));
        ((float2*)g_y)[(size_t)bl * (CC / 2) + oi2] = o;
    }
}

// ---------------- launch -----------------------------------------------------
extern "C" void kernel_launch(void* const* d_in, const int* in_sizes, int n_in,
                              void* d_out, int out_size) {
    const float* x        = (const float*)d_in[0];
    const float* wave_w   = (const float*)d_in[1];
    const float* wave_b   = (const float*)d_in[2];
    const float* kernel_w = (const float*)d_in[3];
    const float* kernel_b = (const float*)d_in[4];
    const float* out_w    = (const float*)d_in[5];
    float* out = (float*)d_out;

    float *p_kmat, *p_y, *p_xt, *p_wk, *p_wo;
    __half* p_xh;
    cudaGetSymbolAddress((void**)&p_kmat, g_kmat);
    cudaGetSymbolAddress((void**)&p_y,    g_y);
    cudaGetSymbolAddress((void**)&p_xt,   g_xt);
    cudaGetSymbolAddress((void**)&p_xh,   g_xh);
    cudaGetSymbolAddress((void**)&p_wk,   g_wk);
    cudaGetSymbolAddress((void**)&p_wo,   g_wo);

    // 1. converts: x -> (tf32, fp16); weights -> tf32
    cvt_x_kernel<<<(BL * CC / 4 + 255) / 256, 256>>>(
        x, p_xt, (__half2*)p_xh, BL * CC / 4);
    cvt_tf32_kernel<<<(HK * CC / 4 + 255) / 256, 256>>>(kernel_w, p_wk, HK * CC / 4);
    cvt_tf32_kernel<<<(CC * CC / 4 + 255) / 256, 256>>>(out_w,    p_wo, CC * CC / 4);

    // 2. wave -> freq/phase (exact fp32 chain)
    constexpr int WAVE_SMEM = 16 * WPITCH * 4;   // ~64.3 KB
    cudaFuncSetAttribute(wave_exact_kernel,
                         cudaFuncAttributeMaxDynamicSharedMemorySize, WAVE_SMEM);
    wave_exact_kernel<<<BL / 16, 256, WAVE_SMEM>>>(x, wave_w, wave_b);

    // 3. kmat = x @ kernel_w^T + kernel_b   [2048 x 512]  (128 blocks)
    gemm_tf32_kernel<64, 128, 2, 4><<<dim3(HK / 128, BL / 64), 256>>>(
        p_xt, p_wk, kernel_b, p_kmat, BL, HK, CC);

    // 4. gather + weighted reduce -> y (fp16 values, tf32-rounded out)
    gather_kernel<<<BL, 256>>>((const __half2*)p_xh);

    // 5. out = y @ out_w^T                   [2048 x 1024]  (128 blocks)
    gemm_tf32_kernel<128, 128, 4, 2><<<dim3(CC / 128, BL / 128), 256>>>(
        p_y, p_wo, nullptr, out, BL, CC, CC);

    (void)in_sizes; (void)n_in; (void)out_size;
}

// round 7
// speedup vs baseline: 2.7047x; 1.0724x over previous
#include <cuda_runtime.h>
#include <cuda_fp16.h>
#include <math.h>
#include <stdint.h>

// Problem constants (fixed by setup_inputs)
namespace {
constexpr int BB = 2;
constexpr int LL = 1024;
constexpr int CC = 1024;
constexpr int HH = 8;
constexpr int DD = 128;   // CC / HH
constexpr int SS = 32;    // sample taps
constexpr int KK = 64;    // kernel taps
constexpr int BL = BB * LL;           // 2048
constexpr int HK = HH * KK;           // 512
constexpr int WPITCH = 1028;          // wave_w smem pitch (floats)
}

// ---------------- scratch (static device globals; no runtime allocation) ----
__device__ float  g_freq [BL * HH];
__device__ float  g_phase[BL * HH];
__device__ float  g_kmat [BL * HK];       // 4 MB
__device__ float  g_y    [BL * CC];       // 8 MB (tf32-rounded)
__device__ float  g_xt   [BL * CC];       // x tf32-rounded (8 MB)
__device__ __half g_xh   [BL * CC];       // x fp16 (4 MB) for gather
__device__ float  g_wk   [HK * CC];       // kernel_w tf32 [N][K]
__device__ float  g_wo   [CC * CC];       // out_w tf32 [N][K]

// ---------------- small helpers ----------------------------------------------
__device__ __forceinline__ uint32_t cvt_tf32(float x) {
    uint32_t r; asm("cvt.rna.tf32.f32 %0, %1;" : "=r"(r) : "f"(x)); return r;
}
__device__ __forceinline__ float cvt_tf32f(float x) {
    return __uint_as_float(cvt_tf32(x));
}
__device__ __forceinline__ uint32_t smem_u32(const void* p) {
    return (uint32_t)__cvta_generic_to_shared(p);
}
__device__ __forceinline__ void cp_async16(uint32_t dst, const void* src) {
    asm volatile("cp.async.cg.shared.global [%0], [%1], 16;" :: "r"(dst), "l"(src));
}

// ---------------- fused converts ----------------------------------------------
// region A: x (tf32 + fp16), region B: kernel_w (tf32), region C: out_w (tf32)
namespace {
constexpr int N4_X = BL * CC / 4;     // 524288
constexpr int N4_K = HK * CC / 4;     // 131072
constexpr int N4_O = CC * CC / 4;     // 262144
constexpr int N4_TOT = N4_X + N4_K + N4_O;
}
__global__ void __launch_bounds__(256) cvt_all_kernel(
    const float* __restrict__ x, const float* __restrict__ kw,
    const float* __restrict__ ow,
    float* __restrict__ xt, __half2* __restrict__ xh,
    float* __restrict__ wk, float* __restrict__ wo) {
    int i = blockIdx.x * 256 + threadIdx.x;
    if (i < N4_X) {
        float4 v = ((const float4*)x)[i];
        float4 t;
        t.x = cvt_tf32f(v.x); t.y = cvt_tf32f(v.y);
        t.z = cvt_tf32f(v.z); t.w = cvt_tf32f(v.w);
        ((float4*)xt)[i] = t;
        xh[2 * i    ] = __floats2half2_rn(v.x, v.y);
        xh[2 * i + 1] = __floats2half2_rn(v.z, v.w);
    } else if (i < N4_X + N4_K) {
        int k = i - N4_X;
        float4 v = ((const float4*)kw)[k];
        v.x = cvt_tf32f(v.x); v.y = cvt_tf32f(v.y);
        v.z = cvt_tf32f(v.z); v.w = cvt_tf32f(v.w);
        ((float4*)wk)[k] = v;
    } else if (i < N4_TOT) {
        int k = i - N4_X - N4_K;
        float4 v = ((const float4*)ow)[k];
        v.x = cvt_tf32f(v.x); v.y = cvt_tf32f(v.y);
        v.z = cvt_tf32f(v.z); v.w = cvt_tf32f(v.w);
        ((float4*)wo)[k] = v;
    }
}

// ---------------- XLA/Eigen fast-tanh f32 ------------------------------------
__device__ __forceinline__ float tanh_xla(float x) {
    float xc = fminf(fmaxf(x, -7.99881172180175781f), 7.99881172180175781f);
    float x2 = __fmul_rn(xc, xc);
    float p = __fmaf_rn(x2, -2.76076847742355e-16f, 2.00018790482477e-13f);
    p = __fmaf_rn(x2, p, -8.60467152213735e-11f);
    p = __fmaf_rn(x2, p,  5.12229709037114e-08f);
    p = __fmaf_rn(x2, p,  1.48572235717979e-05f);
    p = __fmaf_rn(x2, p,  6.37261928875436e-04f);
    p = __fmaf_rn(x2, p,  4.89352455891786e-03f);
    p = __fmul_rn(xc, p);
    float q = __fmaf_rn(x2, 1.19825839466702e-06f, 1.18534705686654e-04f);
    q = __fmaf_rn(x2, q, 2.26843463243900e-03f);
    q = __fmaf_rn(x2, q, 4.89352518554385e-03f);
    float r = __fdiv_rn(p, q);
    return (fabsf(x) < 0.0004f) ? x : r;
}

// ---------------- wave: serial-FMA dots -> freq/phase (FROZEN numerics) ------
// Bit-identical serial k=0..1023 __fmaf_rn chain per output. Both operands
// staged in smem via cp.async (high MLP); 16 rows x 16 outputs = 256 chains.
__global__ void __launch_bounds__(256) wave_exact_kernel(
    const float* __restrict__ x,
    const float* __restrict__ wave_w,   // [16, C]
    const float* __restrict__ wave_b)   // [16] (zeros)
{
    extern __shared__ float sm[];
    float* xs  = sm;                    // [16][1024]
    float* wsm = sm + 16 * CC;          // [16][WPITCH]
    __shared__ float wvs[16][16];

    const int bl0 = blockIdx.x * 16;
    const int tid = threadIdx.x;

    // cp.async fills: x rows (linear) + wave_w (padded pitch)
    const uint32_t xs_base = smem_u32(xs);
    const uint32_t ws_base = smem_u32(wsm);
    #pragma unroll
    for (int i = tid; i < 16 * (CC / 4); i += 256)
        cp_async16(xs_base + i * 16, x + (size_t)bl0 * CC + i * 4);
    #pragma unroll
    for (int i = tid; i < 16 * (CC / 4); i += 256) {
        int r = i >> 8;                 // CC/4 = 256
        int c = i & 255;
        cp_async16(ws_base + (r * WPITCH + c * 4) * 4, wave_w + i * 4);
    }
    asm volatile("cp.async.commit_group;");
    asm volatile("cp.async.wait_group 0;");
    __syncthreads();

    const int j = tid & 15;             // output index
    const int r = tid >> 4;             // local row 0..15
    const float4* wr = (const float4*)(wsm + j * WPITCH);
    const float4* xr = (const float4*)(xs + r * CC);
    float a0 = 0.0f;
    #pragma unroll 8
    for (int k4 = 0; k4 < CC / 4; k4++) {
        float4 wv = wr[k4];
        float4 xv = xr[k4];
        a0 = __fmaf_rn(xv.x, wv.x, a0);
        a0 = __fmaf_rn(xv.y, wv.y, a0);
        a0 = __fmaf_rn(xv.z, wv.z, a0);
        a0 = __fmaf_rn(xv.w, wv.w, a0);
    }
    wvs[r][j] = __fadd_rn(a0, __ldg(wave_b + j));
    __syncthreads();

    if (tid < 128) {                    // elementwise tail: 16 rows x 8 heads
        int rr = tid >> 3;
        int h  = tid & 7;
        float w0 = wvs[rr][2 * h];
        float w1 = wvs[rr][2 * h + 1];
        float t0  = tanh_xla(__fmul_rn(0.5f, w0));
        float sig = __fadd_rn(0.5f, __fmul_rn(0.5f, t0));
        float freq = __fadd_rn(1.0f, __fmul_rn(sig, 15.0f));   // STRICT mul,add
        float t1 = tanh_xla(w1);
        float phase = __fmul_rn(t1, freq);
        g_freq [(bl0 + rr) * HH + h] = freq;
        g_phase[(bl0 + rr) * HH + h] = phase;
    }
}

// ---------------- tf32 tensor-core GEMM (templated tiles) ---------------------
namespace { constexpr int GBK = 16, GPAD = 20; }

template <int BM, int BN, int WM, int WN>
__global__ void __launch_bounds__(256, 1) gemm_tf32_kernel(
    const float* __restrict__ A, const float* __restrict__ Bw,
    const float* __restrict__ bias, float* __restrict__ C,
    int M, int N, int K)
{
    constexpr int WTM = BM / WM;
    constexpr int WTN = BN / WN;
    constexpr int MF = WTM / 16;
    constexpr int NF = WTN / 8;
    static_assert(WM * WN == 8, "8 warps");

    __shared__ float As[2][BM][GPAD];
    __shared__ float Bs[2][BN][GPAD];

    const int tid = threadIdx.x;
    const int m0 = blockIdx.y * BM;
    const int n0 = blockIdx.x * BN;

    const int lane = tid & 31;
    const int g = lane >> 2;
    const int t = lane & 3;
    const int warp = tid >> 5;
    const int m_off = (warp % WM) * WTM;
    const int n_off = (warp / WM) * WTN;

    const uint32_t as_base = smem_u32(&As[0][0][0]);
    const uint32_t bs_base = smem_u32(&Bs[0][0][0]);
    const int NK = K / GBK;

    auto fill = [&](int buf, int k0) {
        #pragma unroll
        for (int i = tid; i < BM * 4; i += 256) {
            int row = i >> 2, ch = i & 3;
            cp_async16(as_base + ((buf * BM + row) * GPAD) * 4 + ch * 16,
                       A + (size_t)(m0 + row) * K + k0 + ch * 4);
        }
        #pragma unroll
        for (int i = tid; i < BN * 4; i += 256) {
            int row = i >> 2, ch = i & 3;
            cp_async16(bs_base + ((buf * BN + row) * GPAD) * 4 + ch * 16,
                       Bw + (size_t)(n0 + row) * K + k0 + ch * 4);
        }
    };

    float c[MF][NF][4];
    #pragma unroll
    for (int i = 0; i < MF; i++)
        #pragma unroll
        for (int jj = 0; jj < NF; jj++)
            #pragma unroll
            for (int q = 0; q < 4; q++) c[i][jj][q] = 0.0f;

    fill(0, 0);
    asm volatile("cp.async.commit_group;");

    for (int it = 0; it < NK; ++it) {
        if (it + 1 < NK) {
            fill((it + 1) & 1, (it + 1) * GBK);
            asm volatile("cp.async.commit_group;");
            asm volatile("cp.async.wait_group 1;");
        } else {
            asm volatile("cp.async.wait_group 0;");
        }
        __syncthreads();

        const int buf = it & 1;
        #pragma unroll
        for (int ks = 0; ks < 2; ks++) {
            const int k8 = ks * 8;
            uint32_t a[MF][4], b[NF][2];
            #pragma unroll
            for (int mf = 0; mf < MF; mf++) {
                const float* ar = &As[buf][m_off + 16 * mf][0];
                a[mf][0] = __float_as_uint(ar[(g     ) * GPAD + k8 + t    ]);
                a[mf][1] = __float_as_uint(ar[(g + 8 ) * GPAD + k8 + t    ]);
                a[mf][2] = __float_as_uint(ar[(g     ) * GPAD + k8 + t + 4]);
                a[mf][3] = __float_as_uint(ar[(g + 8 ) * GPAD + k8 + t + 4]);
            }
            #pragma unroll
            for (int nf = 0; nf < NF; nf++) {
                const float* br = &Bs[buf][n_off + 8 * nf + g][0];
                b[nf][0] = __float_as_uint(br[k8 + t    ]);
                b[nf][1] = __float_as_uint(br[k8 + t + 4]);
            }
            #pragma unroll
            for (int mf = 0; mf < MF; mf++)
                #pragma unroll
                for (int nf = 0; nf < NF; nf++)
                    asm volatile(
                        "mma.sync.aligned.m16n8k8.row.col.f32.tf32.tf32.f32 "
                        "{%0,%1,%2,%3}, {%4,%5,%6,%7}, {%8,%9}, {%0,%1,%2,%3};"
                        : "+f"(c[mf][nf][0]), "+f"(c[mf][nf][1]),
                          "+f"(c[mf][nf][2]), "+f"(c[mf][nf][3])
                        : "r"(a[mf][0]), "r"(a[mf][1]), "r"(a[mf][2]), "r"(a[mf][3]),
                          "r"(b[nf][0]), "r"(b[nf][1]));
        }
        __syncthreads();
    }

    #pragma unroll
    for (int nf = 0; nf < NF; nf++) {
        int col = n0 + n_off + 8 * nf + 2 * t;
        float bb0 = 0.0f, bb1 = 0.0f;
        if (bias) { bb0 = __ldg(bias + col); bb1 = __ldg(bias + col + 1); }
        #pragma unroll
        for (int mf = 0; mf < MF; mf++) {
            int row = m0 + m_off + 16 * mf + g;
            float2 v0 = make_float2(c[mf][nf][0] + bb0, c[mf][nf][1] + bb1);
            *(float2*)(C + (size_t)row * N + col) = v0;
            float2 v1 = make_float2(c[mf][nf][2] + bb0, c[mf][nf][3] + bb1);
            *(float2*)(C + (size_t)(row + 8) * N + col) = v1;
        }
    }
}

// ---------------- gather + weighted sum (fp16 x values, fp32 math) -----------
__global__ void __launch_bounds__(256) gather_kernel(const __half2* __restrict__ xh2)
{
    __shared__ float ws  [HH][SS];
    __shared__ float frs [HH][SS];
    __shared__ int   i0s [HH][SS];   // row offsets in half2 units
    __shared__ int   i1s [HH][SS];

    const int bl = blockIdx.x;
    const int b  = bl >> 10;
    const int l  = bl & (LL - 1);
    const int tid = threadIdx.x;

    {   // per (h,s) tap parameters — FROZEN strict unfused fp32
        int h = tid >> 5;
        int s = tid & 31;
        float freq  = g_freq [bl * HH + h];
        float phase = g_phase[bl * HH + h];
        float tap   = (float)(s - 16) + 0.5f;
        float offs  = __fadd_rn(phase, __fmul_rn(freq, tap));   // NO fma
        float pos   = __fadd_rn((float)l, offs);
        pos = fmaxf(pos, 0.0f);
        pos = fminf(pos, (float)(LL - 1));
        float i0f  = floorf(pos);
        float frac = __fsub_rn(pos, i0f);
        int i0 = (int)i0f;
        int i1 = min(i0 + 1, LL - 1);
        float tb = __fmul_rn(__fadd_rn(offs, 256.0f), 0.125f);
        int bin = (int)floorf(tb);
        bin = max(0, min(bin, KK - 1));
        ws [h][s] = g_kmat[((size_t)bl * HH + h) * KK + bin];
        frs[h][s] = frac;
        i0s[h][s] = i0 * (CC / 2);
        i1s[h][s] = i1 * (CC / 2);
    }
    __syncthreads();

    const __half2* xb = xh2 + (size_t)b * (LL * CC / 2);
    #pragma unroll
    for (int r = 0; r < 2; r++) {
        int oi2 = r * 256 + tid;
        int h   = oi2 >> 6;
        int d2  = oi2 & 63;
        const __half2* base = xb + h * (DD / 2) + d2;
        float acc0 = 0.0f, acc1 = 0.0f;
        #pragma unroll 8
        for (int s = 0; s < SS; s++) {
            float2 f0 = __half22float2(__ldg(base + i0s[h][s]));
            float2 f1 = __half22float2(__ldg(base + i1s[h][s]));
            float fr = frs[h][s];
            float w  = ws [h][s];
            float ga = __fadd_rn(f0.x, __fmul_rn(fr, __fsub_rn(f1.x, f0.x)));
            float gb = __fadd_rn(f0.y, __fmul_rn(fr, __fsub_rn(f1.y, f0.y)));
            acc0 = __fmaf_rn(w, ga, acc0);
            acc1 = __fmaf_rn(w, gb, acc1);
        }
        float2 o = make_float2(cvt_tf32f(acc0), cvt_tf32f(acc1));
        ((float2*)g_y)[(size_t)bl * (CC / 2) + oi2] = o;
    }
}

// ---------------- launch -----------------------------------------------------
extern "C" void kernel_launch(void* const* d_in, const int* in_sizes, int n_in,
                              void* d_out, int out_size) {
    const float* x        = (const float*)d_in[0];
    const float* wave_w   = (const float*)d_in[1];
    const float* wave_b   = (const float*)d_in[2];
    const float* kernel_w = (const float*)d_in[3];
    const float* kernel_b = (const float*)d_in[4];
    const float* out_w    = (const float*)d_in[5];
    float* out = (float*)d_out;

    float *p_kmat, *p_y, *p_xt, *p_wk, *p_wo;
    __half* p_xh;
    cudaGetSymbolAddress((void**)&p_kmat, g_kmat);
    cudaGetSymbolAddress((void**)&p_y,    g_y);
    cudaGetSymbolAddress((void**)&p_xt,   g_xt);
    cudaGetSymbolAddress((void**)&p_xh,   g_xh);
    cudaGetSymbolAddress((void**)&p_wk,   g_wk);
    cudaGetSymbolAddress((void**)&p_wo,   g_wo);

    // 1. fused converts: x -> (tf32, fp16); kernel_w, out_w -> tf32
    cvt_all_kernel<<<(N4_TOT + 255) / 256, 256>>>(
        x, kernel_w, out_w, p_xt, (__half2*)p_xh, p_wk, p_wo);

    // 2. wave -> freq/phase (exact fp32 chain; cp.async-staged smem)
    constexpr int WAVE_SMEM = (16 * CC + 16 * WPITCH) * 4;   // ~130 KB
    cudaFuncSetAttribute(wave_exact_kernel,
                         cudaFuncAttributeMaxDynamicSharedMemorySize, WAVE_SMEM);
    wave_exact_kernel<<<BL / 16, 256, WAVE_SMEM>>>(x, wave_w, wave_b);

    // 3. kmat = x @ kernel_w^T + kernel_b   [2048 x 512]  (128 blocks)
    gemm_tf32_kernel<64, 128, 2, 4><<<dim3(HK / 128, BL / 64), 256>>>(
        p_xt, p_wk, kernel_b, p_kmat, BL, HK, CC);

    // 4. gather + weighted reduce -> y (fp16 values, tf32-rounded out)
    gather_kernel<<<BL, 256>>>((const __half2*)p_xh);

    // 5. out = y @ out_w^T                   [2048 x 1024]  (128 blocks)
    gemm_tf32_kernel<128, 128, 4, 2><<<dim3(CC / 128, BL / 128), 256>>>(
        p_y, p_wo, nullptr, out, BL, CC, CC);

    (void)in_sizes; (void)n_in; (void)out_size;
}

// round 8
// speedup vs baseline: 2.8200x; 1.0426x over previous
#include <cuda_runtime.h>
#include <cuda_fp16.h>
#include <math.h>
#include <stdint.h>

// Problem constants (fixed by setup_inputs)
namespace {
constexpr int BB = 2;
constexpr int LL = 1024;
constexpr int CC = 1024;
constexpr int HH = 8;
constexpr int DD = 128;   // CC / HH
constexpr int SS = 32;    // sample taps
constexpr int KK = 64;    // kernel taps
constexpr int BL = BB * LL;           // 2048
constexpr int HK = HH * KK;           // 512
constexpr int WPITCH = 1028;          // wave_w smem pitch (floats)
}

// ---------------- scratch (static device globals; no runtime allocation) ----
__device__ float  g_freq [BL * HH];
__device__ float  g_phase[BL * HH];
__device__ float  g_kmat [BL * HK];       // 4 MB
__device__ float  g_y    [BL * CC];       // 8 MB (tf32-rounded)
__device__ float  g_xt   [BL * CC];       // x tf32-rounded (8 MB)
__device__ __half g_xh   [BL * CC];       // x fp16 (4 MB) for gather
__device__ float  g_wk   [HK * CC];       // kernel_w tf32 [N][K]
__device__ float  g_wo   [CC * CC];       // out_w tf32 [N][K]

// ---------------- small helpers ----------------------------------------------
__device__ __forceinline__ uint32_t cvt_tf32(float x) {
    uint32_t r; asm("cvt.rna.tf32.f32 %0, %1;" : "=r"(r) : "f"(x)); return r;
}
__device__ __forceinline__ float cvt_tf32f(float x) {
    return __uint_as_float(cvt_tf32(x));
}
__device__ __forceinline__ uint32_t smem_u32(const void* p) {
    return (uint32_t)__cvta_generic_to_shared(p);
}
__device__ __forceinline__ void cp_async16(uint32_t dst, const void* src) {
    asm volatile("cp.async.cg.shared.global [%0], [%1], 16;" :: "r"(dst), "l"(src));
}

// ---------------- fused converts ----------------------------------------------
namespace {
constexpr int N4_X = BL * CC / 4;     // 524288
constexpr int N4_K = HK * CC / 4;     // 131072
constexpr int N4_O = CC * CC / 4;     // 262144
constexpr int N4_TOT = N4_X + N4_K + N4_O;
}
__global__ void __launch_bounds__(256) cvt_all_kernel(
    const float* __restrict__ x, const float* __restrict__ kw,
    const float* __restrict__ ow,
    float* __restrict__ xt, __half2* __restrict__ xh,
    float* __restrict__ wk, float* __restrict__ wo) {
    int i = blockIdx.x * 256 + threadIdx.x;
    if (i < N4_X) {
        float4 v = ((const float4*)x)[i];
        float4 t;
        t.x = cvt_tf32f(v.x); t.y = cvt_tf32f(v.y);
        t.z = cvt_tf32f(v.z); t.w = cvt_tf32f(v.w);
        ((float4*)xt)[i] = t;
        xh[2 * i    ] = __floats2half2_rn(v.x, v.y);
        xh[2 * i + 1] = __floats2half2_rn(v.z, v.w);
    } else if (i < N4_X + N4_K) {
        int k = i - N4_X;
        float4 v = ((const float4*)kw)[k];
        v.x = cvt_tf32f(v.x); v.y = cvt_tf32f(v.y);
        v.z = cvt_tf32f(v.z); v.w = cvt_tf32f(v.w);
        ((float4*)wk)[k] = v;
    } else if (i < N4_TOT) {
        int k = i - N4_X - N4_K;
        float4 v = ((const float4*)ow)[k];
        v.x = cvt_tf32f(v.x); v.y = cvt_tf32f(v.y);
        v.z = cvt_tf32f(v.z); v.w = cvt_tf32f(v.w);
        ((float4*)wo)[k] = v;
    }
}

// ---------------- XLA/Eigen fast-tanh f32 ------------------------------------
__device__ __forceinline__ float tanh_xla(float x) {
    float xc = fminf(fmaxf(x, -7.99881172180175781f), 7.99881172180175781f);
    float x2 = __fmul_rn(xc, xc);
    float p = __fmaf_rn(x2, -2.76076847742355e-16f, 2.00018790482477e-13f);
    p = __fmaf_rn(x2, p, -8.60467152213735e-11f);
    p = __fmaf_rn(x2, p,  5.12229709037114e-08f);
    p = __fmaf_rn(x2, p,  1.48572235717979e-05f);
    p = __fmaf_rn(x2, p,  6.37261928875436e-04f);
    p = __fmaf_rn(x2, p,  4.89352455891786e-03f);
    p = __fmul_rn(xc, p);
    float q = __fmaf_rn(x2, 1.19825839466702e-06f, 1.18534705686654e-04f);
    q = __fmaf_rn(x2, q, 2.26843463243900e-03f);
    q = __fmaf_rn(x2, q, 4.89352518554385e-03f);
    float r = __fdiv_rn(p, q);
    return (fabsf(x) < 0.0004f) ? x : r;
}

// ---------------- wave: serial-FMA dots -> freq/phase (FROZEN numerics) ------
__global__ void __launch_bounds__(256) wave_exact_kernel(
    const float* __restrict__ x,
    const float* __restrict__ wave_w,   // [16, C]
    const float* __restrict__ wave_b)   // [16] (zeros)
{
    extern __shared__ float sm[];
    float* xs  = sm;                    // [16][1024]
    float* wsm = sm + 16 * CC;          // [16][WPITCH]
    __shared__ float wvs[16][16];

    const int bl0 = blockIdx.x * 16;
    const int tid = threadIdx.x;

    const uint32_t xs_base = smem_u32(xs);
    const uint32_t ws_base = smem_u32(wsm);
    #pragma unroll
    for (int i = tid; i < 16 * (CC / 4); i += 256)
        cp_async16(xs_base + i * 16, x + (size_t)bl0 * CC + i * 4);
    #pragma unroll
    for (int i = tid; i < 16 * (CC / 4); i += 256) {
        int r = i >> 8;
        int c = i & 255;
        cp_async16(ws_base + (r * WPITCH + c * 4) * 4, wave_w + i * 4);
    }
    asm volatile("cp.async.commit_group;");
    asm volatile("cp.async.wait_group 0;");
    __syncthreads();

    const int j = tid & 15;
    const int r = tid >> 4;
    const float4* wr = (const float4*)(wsm + j * WPITCH);
    const float4* xr = (const float4*)(xs + r * CC);
    float a0 = 0.0f;
    #pragma unroll 8
    for (int k4 = 0; k4 < CC / 4; k4++) {
        float4 wv = wr[k4];
        float4 xv = xr[k4];
        a0 = __fmaf_rn(xv.x, wv.x, a0);
        a0 = __fmaf_rn(xv.y, wv.y, a0);
        a0 = __fmaf_rn(xv.z, wv.z, a0);
        a0 = __fmaf_rn(xv.w, wv.w, a0);
    }
    wvs[r][j] = __fadd_rn(a0, __ldg(wave_b + j));
    __syncthreads();

    if (tid < 128) {
        int rr = tid >> 3;
        int h  = tid & 7;
        float w0 = wvs[rr][2 * h];
        float w1 = wvs[rr][2 * h + 1];
        float t0  = tanh_xla(__fmul_rn(0.5f, w0));
        float sig = __fadd_rn(0.5f, __fmul_rn(0.5f, t0));
        float freq = __fadd_rn(1.0f, __fmul_rn(sig, 15.0f));   // STRICT mul,add
        float t1 = tanh_xla(w1);
        float phase = __fmul_rn(t1, freq);
        g_freq [(bl0 + rr) * HH + h] = freq;
        g_phase[(bl0 + rr) * HH + h] = phase;
    }
}

// ---------------- tf32 tensor-core GEMM (templated tiles) ---------------------
namespace { constexpr int GBK = 16, GPAD = 20; }

template <int BM, int BN, int WM, int WN>
__global__ void __launch_bounds__(256, 1) gemm_tf32_kernel(
    const float* __restrict__ A, const float* __restrict__ Bw,
    const float* __restrict__ bias, float* __restrict__ C,
    int M, int N, int K)
{
    constexpr int WTM = BM / WM;
    constexpr int WTN = BN / WN;
    constexpr int MF = WTM / 16;
    constexpr int NF = WTN / 8;
    static_assert(WM * WN == 8, "8 warps");

    __shared__ float As[2][BM][GPAD];
    __shared__ float Bs[2][BN][GPAD];

    const int tid = threadIdx.x;
    const int m0 = blockIdx.y * BM;
    const int n0 = blockIdx.x * BN;

    const int lane = tid & 31;
    const int g = lane >> 2;
    const int t = lane & 3;
    const int warp = tid >> 5;
    const int m_off = (warp % WM) * WTM;
    const int n_off = (warp / WM) * WTN;

    const uint32_t as_base = smem_u32(&As[0][0][0]);
    const uint32_t bs_base = smem_u32(&Bs[0][0][0]);
    const int NK = K / GBK;

    auto fill = [&](int buf, int k0) {
        #pragma unroll
        for (int i = tid; i < BM * 4; i += 256) {
            int row = i >> 2, ch = i & 3;
            cp_async16(as_base + ((buf * BM + row) * GPAD) * 4 + ch * 16,
                       A + (size_t)(m0 + row) * K + k0 + ch * 4);
        }
        #pragma unroll
        for (int i = tid; i < BN * 4; i += 256) {
            int row = i >> 2, ch = i & 3;
            cp_async16(bs_base + ((buf * BN + row) * GPAD) * 4 + ch * 16,
                       Bw + (size_t)(n0 + row) * K + k0 + ch * 4);
        }
    };

    float c[MF][NF][4];
    #pragma unroll
    for (int i = 0; i < MF; i++)
        #pragma unroll
        for (int jj = 0; jj < NF; jj++)
            #pragma unroll
            for (int q = 0; q < 4; q++) c[i][jj][q] = 0.0f;

    fill(0, 0);
    asm volatile("cp.async.commit_group;");

    for (int it = 0; it < NK; ++it) {
        if (it + 1 < NK) {
            fill((it + 1) & 1, (it + 1) * GBK);
            asm volatile("cp.async.commit_group;");
            asm volatile("cp.async.wait_group 1;");
        } else {
            asm volatile("cp.async.wait_group 0;");
        }
        __syncthreads();

        const int buf = it & 1;
        #pragma unroll
        for (int ks = 0; ks < 2; ks++) {
            const int k8 = ks * 8;
            uint32_t a[MF][4], b[NF][2];
            #pragma unroll
            for (int mf = 0; mf < MF; mf++) {
                const float* ar = &As[buf][m_off + 16 * mf][0];
                a[mf][0] = __float_as_uint(ar[(g     ) * GPAD + k8 + t    ]);
                a[mf][1] = __float_as_uint(ar[(g + 8 ) * GPAD + k8 + t    ]);
                a[mf][2] = __float_as_uint(ar[(g     ) * GPAD + k8 + t + 4]);
                a[mf][3] = __float_as_uint(ar[(g + 8 ) * GPAD + k8 + t + 4]);
            }
            #pragma unroll
            for (int nf = 0; nf < NF; nf++) {
                const float* br = &Bs[buf][n_off + 8 * nf + g][0];
                b[nf][0] = __float_as_uint(br[k8 + t    ]);
                b[nf][1] = __float_as_uint(br[k8 + t + 4]);
            }
            #pragma unroll
            for (int mf = 0; mf < MF; mf++)
                #pragma unroll
                for (int nf = 0; nf < NF; nf++)
                    asm volatile(
                        "mma.sync.aligned.m16n8k8.row.col.f32.tf32.tf32.f32 "
                        "{%0,%1,%2,%3}, {%4,%5,%6,%7}, {%8,%9}, {%0,%1,%2,%3};"
                        : "+f"(c[mf][nf][0]), "+f"(c[mf][nf][1]),
                          "+f"(c[mf][nf][2]), "+f"(c[mf][nf][3])
                        : "r"(a[mf][0]), "r"(a[mf][1]), "r"(a[mf][2]), "r"(a[mf][3]),
                          "r"(b[nf][0]), "r"(b[nf][1]));
        }
        __syncthreads();
    }

    #pragma unroll
    for (int nf = 0; nf < NF; nf++) {
        int col = n0 + n_off + 8 * nf + 2 * t;
        float bb0 = 0.0f, bb1 = 0.0f;
        if (bias) { bb0 = __ldg(bias + col); bb1 = __ldg(bias + col + 1); }
        #pragma unroll
        for (int mf = 0; mf < MF; mf++) {
            int row = m0 + m_off + 16 * mf + g;
            float2 v0 = make_float2(c[mf][nf][0] + bb0, c[mf][nf][1] + bb1);
            *(float2*)(C + (size_t)row * N + col) = v0;
            float2 v1 = make_float2(c[mf][nf][2] + bb0, c[mf][nf][3] + bb1);
            *(float2*)(C + (size_t)(row + 8) * N + col) = v1;
        }
    }
}

// ---------------- gather: half2 interp, fp32 accumulate ----------------------
__global__ void __launch_bounds__(256) gather_kernel(const __half2* __restrict__ xh2)
{
    __shared__ float   ws  [HH][SS];
    __shared__ __half2 fr2s[HH][SS];
    __shared__ int     i0s [HH][SS];   // row offsets in half2 units
    __shared__ int     i1s [HH][SS];

    const int bl = blockIdx.x;
    const int b  = bl >> 10;
    const int l  = bl & (LL - 1);
    const int tid = threadIdx.x;

    {   // per (h,s) tap parameters — FROZEN strict unfused fp32
        int h = tid >> 5;
        int s = tid & 31;
        float freq  = g_freq [bl * HH + h];
        float phase = g_phase[bl * HH + h];
        float tap   = (float)(s - 16) + 0.5f;
        float offs  = __fadd_rn(phase, __fmul_rn(freq, tap));   // NO fma
        float pos   = __fadd_rn((float)l, offs);
        pos = fmaxf(pos, 0.0f);
        pos = fminf(pos, (float)(LL - 1));
        float i0f  = floorf(pos);
        float frac = __fsub_rn(pos, i0f);
        int i0 = (int)i0f;
        int i1 = min(i0 + 1, LL - 1);
        float tb = __fmul_rn(__fadd_rn(offs, 256.0f), 0.125f);
        int bin = (int)floorf(tb);
        bin = max(0, min(bin, KK - 1));
        ws  [h][s] = g_kmat[((size_t)bl * HH + h) * KK + bin];
        fr2s[h][s] = __float2half2_rn(frac);
        i0s [h][s] = i0 * (CC / 2);
        i1s [h][s] = i1 * (CC / 2);
    }
    __syncthreads();

    const __half2* xb = xh2 + (size_t)b * (LL * CC / 2);
    #pragma unroll
    for (int r = 0; r < 2; r++) {
        int oi2 = r * 256 + tid;
        int h   = oi2 >> 6;
        int d2  = oi2 & 63;
        const __half2* base = xb + h * (DD / 2) + d2;
        float acc0 = 0.0f, acc1 = 0.0f;
        #pragma unroll 8
        for (int s = 0; s < SS; s++) {
            __half2 f0 = __ldg(base + i0s[h][s]);
            __half2 f1 = __ldg(base + i1s[h][s]);
            __half2 gh = __hfma2(fr2s[h][s], __hsub2(f1, f0), f0);
            float2 gf = __half22float2(gh);
            float w = ws[h][s];
            acc0 = __fmaf_rn(w, gf.x, acc0);
            acc1 = __fmaf_rn(w, gf.y, acc1);
        }
        float2 o = make_float2(cvt_tf32f(acc0), cvt_tf32f(acc1));
        ((float2*)g_y)[(size_t)bl * (CC / 2) + oi2] = o;
    }
}

// ---------------- launch -----------------------------------------------------
extern "C" void kernel_launch(void* const* d_in, const int* in_sizes, int n_in,
                              void* d_out, int out_size) {
    const float* x        = (const float*)d_in[0];
    const float* wave_w   = (const float*)d_in[1];
    const float* wave_b   = (const float*)d_in[2];
    const float* kernel_w = (const float*)d_in[3];
    const float* kernel_b = (const float*)d_in[4];
    const float* out_w    = (const float*)d_in[5];
    float* out = (float*)d_out;

    float *p_kmat, *p_y, *p_xt, *p_wk, *p_wo;
    __half* p_xh;
    cudaGetSymbolAddress((void**)&p_kmat, g_kmat);
    cudaGetSymbolAddress((void**)&p_y,    g_y);
    cudaGetSymbolAddress((void**)&p_xt,   g_xt);
    cudaGetSymbolAddress((void**)&p_xh,   g_xh);
    cudaGetSymbolAddress((void**)&p_wk,   g_wk);
    cudaGetSymbolAddress((void**)&p_wo,   g_wo);

    // fork a side stream for the wave kernel (depends only on raw x).
    // Created per-call and intentionally not destroyed (capture-legal; the
    // handful of capture/correctness calls leak a few KB of host handles).
    cudaStream_t s_wave;
    cudaEvent_t ev_fork, ev_join;
    cudaStreamCreateWithFlags(&s_wave, cudaStreamNonBlocking);
    cudaEventCreateWithFlags(&ev_fork, cudaEventDisableTiming);
    cudaEventCreateWithFlags(&ev_join, cudaEventDisableTiming);

    constexpr int WAVE_SMEM = (16 * CC + 16 * WPITCH) * 4;   // ~130 KB
    cudaFuncSetAttribute(wave_exact_kernel,
                         cudaFuncAttributeMaxDynamicSharedMemorySize, WAVE_SMEM);

    // fork: wave on side stream
    cudaEventRecord(ev_fork, 0);
    cudaStreamWaitEvent(s_wave, ev_fork, 0);
    wave_exact_kernel<<<BL / 16, 256, WAVE_SMEM, s_wave>>>(x, wave_w, wave_b);
    cudaEventRecord(ev_join, s_wave);

    // main stream: converts then kmat GEMM
    cvt_all_kernel<<<(N4_TOT + 255) / 256, 256>>>(
        x, kernel_w, out_w, p_xt, (__half2*)p_xh, p_wk, p_wo);
    gemm_tf32_kernel<64, 128, 2, 4><<<dim3(HK / 128, BL / 64), 256>>>(
        p_xt, p_wk, kernel_b, p_kmat, BL, HK, CC);

    // join: gather needs wave + kmat + xh
    cudaStreamWaitEvent(0, ev_join, 0);
    gather_kernel<<<BL, 256>>>((const __half2*)p_xh);

    gemm_tf32_kernel<128, 128, 4, 2><<<dim3(CC / 128, BL / 128), 256>>>(
        p_y, p_wo, nullptr, out, BL, CC, CC);

    (void)in_sizes; (void)n_in; (void)out_size;
}

// round 9
// speedup vs baseline: 4.3922x; 1.5575x over previous
#include <cuda_runtime.h>
#include <cuda_fp16.h>
#include <math.h>
#include <stdint.h>

// Problem constants (fixed by setup_inputs)
namespace {
constexpr int BB = 2;
constexpr int LL = 1024;
constexpr int CC = 1024;
constexpr int HH = 8;
constexpr int DD = 128;   // CC / HH
constexpr int SS = 32;    // sample taps
constexpr int KK = 64;    // kernel taps
constexpr int BL = BB * LL;           // 2048
constexpr int HK = HH * KK;           // 512
constexpr int WPITCH = 1028;          // wave_w smem pitch (floats)
}

// ---------------- scratch (static device globals; no runtime allocation) ----
__device__ float  g_freq [BL * HH];
__device__ float  g_phase[BL * HH];
__device__ float  g_kmat [BL * HK];       // 4 MB (fp32 accum out of f16 GEMM)
__device__ __half g_yh   [BL * CC];       // 4 MB y (fp16)
__device__ __half g_xh   [BL * CC];       // 4 MB x (fp16): gather + kmat A
__device__ __half g_wkh  [HK * CC];       // kernel_w fp16 [N][K]
__device__ __half g_woh  [CC * CC];       // out_w fp16 [N][K]

// ---------------- small helpers ----------------------------------------------
__device__ __forceinline__ uint32_t smem_u32(const void* p) {
    return (uint32_t)__cvta_generic_to_shared(p);
}
__device__ __forceinline__ void cp_async16(uint32_t dst, const void* src) {
    asm volatile("cp.async.cg.shared.global [%0], [%1], 16;" :: "r"(dst), "l"(src));
}

// ---------------- fused converts: fp32 -> fp16 --------------------------------
namespace {
constexpr int N4_X = BL * CC / 4;     // 524288
constexpr int N4_K = HK * CC / 4;     // 131072
constexpr int N4_O = CC * CC / 4;     // 262144
constexpr int N4_TOT = N4_X + N4_K + N4_O;
}
__global__ void __launch_bounds__(256) cvt_all_kernel(
    const float* __restrict__ x, const float* __restrict__ kw,
    const float* __restrict__ ow,
    uint2* __restrict__ xh, uint2* __restrict__ wkh, uint2* __restrict__ woh) {
    int i = blockIdx.x * 256 + threadIdx.x;
    const float* src;
    uint2* dst;
    int k;
    if (i < N4_X)            { src = x;  dst = xh;  k = i; }
    else if (i < N4_X + N4_K){ src = kw; dst = wkh; k = i - N4_X; }
    else if (i < N4_TOT)     { src = ow; dst = woh; k = i - N4_X - N4_K; }
    else return;
    float4 v = ((const float4*)src)[k];
    __half2 h0 = __floats2half2_rn(v.x, v.y);
    __half2 h1 = __floats2half2_rn(v.z, v.w);
    uint2 o;
    o.x = *(uint32_t*)&h0;
    o.y = *(uint32_t*)&h1;
    dst[k] = o;
}

// ---------------- XLA/Eigen fast-tanh f32 ------------------------------------
__device__ __forceinline__ float tanh_xla(float x) {
    float xc = fminf(fmaxf(x, -7.99881172180175781f), 7.99881172180175781f);
    float x2 = __fmul_rn(xc, xc);
    float p = __fmaf_rn(x2, -2.76076847742355e-16f, 2.00018790482477e-13f);
    p = __fmaf_rn(x2, p, -8.60467152213735e-11f);
    p = __fmaf_rn(x2, p,  5.12229709037114e-08f);
    p = __fmaf_rn(x2, p,  1.48572235717979e-05f);
    p = __fmaf_rn(x2, p,  6.37261928875436e-04f);
    p = __fmaf_rn(x2, p,  4.89352455891786e-03f);
    p = __fmul_rn(xc, p);
    float q = __fmaf_rn(x2, 1.19825839466702e-06f, 1.18534705686654e-04f);
    q = __fmaf_rn(x2, q, 2.26843463243900e-03f);
    q = __fmaf_rn(x2, q, 4.89352518554385e-03f);
    float r = __fdiv_rn(p, q);
    return (fabsf(x) < 0.0004f) ? x : r;
}

// ---------------- wave: serial-FMA dots -> freq/phase (FROZEN numerics) ------
__global__ void __launch_bounds__(256) wave_exact_kernel(
    const float* __restrict__ x,
    const float* __restrict__ wave_w,   // [16, C]
    const float* __restrict__ wave_b)   // [16] (zeros)
{
    extern __shared__ float sm[];
    float* xs  = sm;                    // [16][1024]
    float* wsm = sm + 16 * CC;          // [16][WPITCH]
    __shared__ float wvs[16][16];

    const int bl0 = blockIdx.x * 16;
    const int tid = threadIdx.x;

    const uint32_t xs_base = smem_u32(xs);
    const uint32_t ws_base = smem_u32(wsm);
    #pragma unroll
    for (int i = tid; i < 16 * (CC / 4); i += 256)
        cp_async16(xs_base + i * 16, x + (size_t)bl0 * CC + i * 4);
    #pragma unroll
    for (int i = tid; i < 16 * (CC / 4); i += 256) {
        int r = i >> 8;
        int c = i & 255;
        cp_async16(ws_base + (r * WPITCH + c * 4) * 4, wave_w + i * 4);
    }
    asm volatile("cp.async.commit_group;");
    asm volatile("cp.async.wait_group 0;");
    __syncthreads();

    const int j = tid & 15;
    const int r = tid >> 4;
    const float4* wr = (const float4*)(wsm + j * WPITCH);
    const float4* xr = (const float4*)(xs + r * CC);
    float a0 = 0.0f;
    #pragma unroll 8
    for (int k4 = 0; k4 < CC / 4; k4++) {
        float4 wv = wr[k4];
        float4 xv = xr[k4];
        a0 = __fmaf_rn(xv.x, wv.x, a0);
        a0 = __fmaf_rn(xv.y, wv.y, a0);
        a0 = __fmaf_rn(xv.z, wv.z, a0);
        a0 = __fmaf_rn(xv.w, wv.w, a0);
    }
    wvs[r][j] = __fadd_rn(a0, __ldg(wave_b + j));
    __syncthreads();

    if (tid < 128) {
        int rr = tid >> 3;
        int h  = tid & 7;
        float w0 = wvs[rr][2 * h];
        float w1 = wvs[rr][2 * h + 1];
        float t0  = tanh_xla(__fmul_rn(0.5f, w0));
        float sig = __fadd_rn(0.5f, __fmul_rn(0.5f, t0));
        float freq = __fadd_rn(1.0f, __fmul_rn(sig, 15.0f));   // STRICT mul,add
        float t1 = tanh_xla(w1);
        float phase = __fmul_rn(t1, freq);
        g_freq [(bl0 + rr) * HH + h] = freq;
        g_phase[(bl0 + rr) * HH + h] = phase;
    }
}

// ---------------- fp16 tensor-core GEMM (m16n8k16, fp32 accum) ----------------
// C[M][N](f32) = A[M][K](f16) * B[N][K]^T(f16) (+bias[n]).
namespace { constexpr int HBK = 32, HPITCH = 40; }  // halves; 80B rows conflict-free

template <int BM, int BN, int WM, int WN>
__global__ void __launch_bounds__(256, 1) gemm_f16_kernel(
    const __half* __restrict__ A, const __half* __restrict__ Bw,
    const float* __restrict__ bias, float* __restrict__ C,
    int M, int N, int K)
{
    constexpr int WTM = BM / WM;
    constexpr int WTN = BN / WN;
    constexpr int MF = WTM / 16;
    constexpr int NF = WTN / 8;
    static_assert(WM * WN == 8, "8 warps");

    __shared__ __half As[2][BM][HPITCH];
    __shared__ __half Bs[2][BN][HPITCH];

    const int tid = threadIdx.x;
    const int m0 = blockIdx.y * BM;
    const int n0 = blockIdx.x * BN;

    const int lane = tid & 31;
    const int g = lane >> 2;
    const int t = lane & 3;
    const int warp = tid >> 5;
    const int m_off = (warp % WM) * WTM;
    const int n_off = (warp / WM) * WTN;

    const uint32_t as_base = smem_u32(&As[0][0][0]);
    const uint32_t bs_base = smem_u32(&Bs[0][0][0]);
    const int NK = K / HBK;

    auto fill = [&](int buf, int k0) {
        #pragma unroll
        for (int i = tid; i < BM * 4; i += 256) {
            int row = i >> 2, ch = i & 3;
            cp_async16(as_base + ((buf * BM + row) * HPITCH) * 2 + ch * 16,
                       A + (size_t)(m0 + row) * K + k0 + ch * 8);
        }
        #pragma unroll
        for (int i = tid; i < BN * 4; i += 256) {
            int row = i >> 2, ch = i & 3;
            cp_async16(bs_base + ((buf * BN + row) * HPITCH) * 2 + ch * 16,
                       Bw + (size_t)(n0 + row) * K + k0 + ch * 8);
        }
    };

    float c[MF][NF][4];
    #pragma unroll
    for (int i = 0; i < MF; i++)
        #pragma unroll
        for (int jj = 0; jj < NF; jj++)
            #pragma unroll
            for (int q = 0; q < 4; q++) c[i][jj][q] = 0.0f;

    fill(0, 0);
    asm volatile("cp.async.commit_group;");

    for (int it = 0; it < NK; ++it) {
        if (it + 1 < NK) {
            fill((it + 1) & 1, (it + 1) * HBK);
            asm volatile("cp.async.commit_group;");
            asm volatile("cp.async.wait_group 1;");
        } else {
            asm volatile("cp.async.wait_group 0;");
        }
        __syncthreads();

        const int buf = it & 1;
        #pragma unroll
        for (int ks = 0; ks < 2; ks++) {
            const int k16 = ks * 16;
            uint32_t a[MF][4], b[NF][2];
            #pragma unroll
            for (int mf = 0; mf < MF; mf++) {
                const __half* r0 = &As[buf][m_off + 16 * mf + g    ][k16 + 2 * t];
                const __half* r1 = &As[buf][m_off + 16 * mf + g + 8][k16 + 2 * t];
                a[mf][0] = *(const uint32_t*)(r0);
                a[mf][1] = *(const uint32_t*)(r1);
                a[mf][2] = *(const uint32_t*)(r0 + 8);
                a[mf][3] = *(const uint32_t*)(r1 + 8);
            }
            #pragma unroll
            for (int nf = 0; nf < NF; nf++) {
                const __half* br = &Bs[buf][n_off + 8 * nf + g][k16 + 2 * t];
                b[nf][0] = *(const uint32_t*)(br);
                b[nf][1] = *(const uint32_t*)(br + 8);
            }
            #pragma unroll
            for (int mf = 0; mf < MF; mf++)
                #pragma unroll
                for (int nf = 0; nf < NF; nf++)
                    asm volatile(
                        "mma.sync.aligned.m16n8k16.row.col.f32.f16.f16.f32 "
                        "{%0,%1,%2,%3}, {%4,%5,%6,%7}, {%8,%9}, {%0,%1,%2,%3};"
                        : "+f"(c[mf][nf][0]), "+f"(c[mf][nf][1]),
                          "+f"(c[mf][nf][2]), "+f"(c[mf][nf][3])
                        : "r"(a[mf][0]), "r"(a[mf][1]), "r"(a[mf][2]), "r"(a[mf][3]),
                          "r"(b[nf][0]), "r"(b[nf][1]));
        }
        __syncthreads();
    }

    #pragma unroll
    for (int nf = 0; nf < NF; nf++) {
        int col = n0 + n_off + 8 * nf + 2 * t;
        float bb0 = 0.0f, bb1 = 0.0f;
        if (bias) { bb0 = __ldg(bias + col); bb1 = __ldg(bias + col + 1); }
        #pragma unroll
        for (int mf = 0; mf < MF; mf++) {
            int row = m0 + m_off + 16 * mf + g;
            float2 v0 = make_float2(c[mf][nf][0] + bb0, c[mf][nf][1] + bb1);
            *(float2*)(C + (size_t)row * N + col) = v0;
            float2 v1 = make_float2(c[mf][nf][2] + bb0, c[mf][nf][3] + bb1);
            *(float2*)(C + (size_t)(row + 8) * N + col) = v1;
        }
    }
}

// ---------------- gather: uint2 (4ch) loads, half2 interp, fp32 accum ---------
__global__ void __launch_bounds__(256) gather_kernel(const __half* __restrict__ xh)
{
    __shared__ float   ws  [HH][SS];
    __shared__ __half2 fr2s[HH][SS];
    __shared__ int     i0s [HH][SS];   // row offsets in uint2 units (i*CC/4)
    __shared__ int     i1s [HH][SS];

    const int bl = blockIdx.x;
    const int b  = bl >> 10;
    const int l  = bl & (LL - 1);
    const int tid = threadIdx.x;

    {   // per (h,s) tap parameters — FROZEN strict unfused fp32
        int h = tid >> 5;
        int s = tid & 31;
        float freq  = g_freq [bl * HH + h];
        float phase = g_phase[bl * HH + h];
        float tap   = (float)(s - 16) + 0.5f;
        float offs  = __fadd_rn(phase, __fmul_rn(freq, tap));   // NO fma
        float pos   = __fadd_rn((float)l, offs);
        pos = fmaxf(pos, 0.0f);
        pos = fminf(pos, (float)(LL - 1));
        float i0f  = floorf(pos);
        float frac = __fsub_rn(pos, i0f);
        int i0 = (int)i0f;
        int i1 = min(i0 + 1, LL - 1);
        float tb = __fmul_rn(__fadd_rn(offs, 256.0f), 0.125f);
        int bin = (int)floorf(tb);
        bin = max(0, min(bin, KK - 1));
        ws  [h][s] = g_kmat[((size_t)bl * HH + h) * KK + bin];
        fr2s[h][s] = __float2half2_rn(frac);
        i0s [h][s] = i0 * (CC / 4);
        i1s [h][s] = i1 * (CC / 4);
    }
    __syncthreads();

    // 256 threads x 4 channels = 1024 channels
    const uint2* xb = (const uint2*)(xh + (size_t)b * (LL * CC));
    const int h  = tid >> 5;           // 32 uint2 per head (128 ch)
    const int d4 = tid & 31;
    const uint2* base = xb + h * (DD / 4) + d4;
    float acc0 = 0.0f, acc1 = 0.0f, acc2 = 0.0f, acc3 = 0.0f;
    #pragma unroll 8
    for (int s = 0; s < SS; s++) {
        uint2 u0 = __ldg(base + i0s[h][s]);
        uint2 u1 = __ldg(base + i1s[h][s]);
        __half2 fr = fr2s[h][s];
        float w = ws[h][s];
        __half2 f0a = *(__half2*)&u0.x, f0b = *(__half2*)&u0.y;
        __half2 f1a = *(__half2*)&u1.x, f1b = *(__half2*)&u1.y;
        __half2 ga = __hfma2(fr, __hsub2(f1a, f0a), f0a);
        __half2 gb = __hfma2(fr, __hsub2(f1b, f0b), f0b);
        float2 fa = __half22float2(ga);
        float2 fb = __half22float2(gb);
        acc0 = __fmaf_rn(w, fa.x, acc0);
        acc1 = __fmaf_rn(w, fa.y, acc1);
        acc2 = __fmaf_rn(w, fb.x, acc2);
        acc3 = __fmaf_rn(w, fb.y, acc3);
    }
    __half2 o0 = __floats2half2_rn(acc0, acc1);
    __half2 o1 = __floats2half2_rn(acc2, acc3);
    uint2 o;
    o.x = *(uint32_t*)&o0;
    o.y = *(uint32_t*)&o1;
    ((uint2*)g_yh)[(size_t)bl * (CC / 4) + tid] = o;
}

// ---------------- launch -----------------------------------------------------
extern "C" void kernel_launch(void* const* d_in, const int* in_sizes, int n_in,
                              void* d_out, int out_size) {
    const float* x        = (const float*)d_in[0];
    const float* wave_w   = (const float*)d_in[1];
    const float* wave_b   = (const float*)d_in[2];
    const float* kernel_w = (const float*)d_in[3];
    const float* kernel_b = (const float*)d_in[4];
    const float* out_w    = (const float*)d_in[5];
    float* out = (float*)d_out;

    float *p_kmat;
    __half *p_xh, *p_yh, *p_wkh, *p_woh;
    cudaGetSymbolAddress((void**)&p_kmat, g_kmat);
    cudaGetSymbolAddress((void**)&p_xh,   g_xh);
    cudaGetSymbolAddress((void**)&p_yh,   g_yh);
    cudaGetSymbolAddress((void**)&p_wkh,  g_wkh);
    cudaGetSymbolAddress((void**)&p_woh,  g_woh);

    // fork a side stream for the wave kernel (depends only on raw x).
    cudaStream_t s_wave;
    cudaEvent_t ev_fork, ev_join;
    cudaStreamCreateWithFlags(&s_wave, cudaStreamNonBlocking);
    cudaEventCreateWithFlags(&ev_fork, cudaEventDisableTiming);
    cudaEventCreateWithFlags(&ev_join, cudaEventDisableTiming);

    constexpr int WAVE_SMEM = (16 * CC + 16 * WPITCH) * 4;   // ~130 KB
    cudaFuncSetAttribute(wave_exact_kernel,
                         cudaFuncAttributeMaxDynamicSharedMemorySize, WAVE_SMEM);

    cudaEventRecord(ev_fork, 0);
    cudaStreamWaitEvent(s_wave, ev_fork, 0);
    wave_exact_kernel<<<BL / 16, 256, WAVE_SMEM, s_wave>>>(x, wave_w, wave_b);
    cudaEventRecord(ev_join, s_wave);

    // main stream: converts, kmat GEMM
    cvt_all_kernel<<<(N4_TOT + 255) / 256, 256>>>(
        x, kernel_w, out_w, (uint2*)p_xh, (uint2*)p_wkh, (uint2*)p_woh);
    gemm_f16_kernel<64, 128, 2, 4><<<dim3(HK / 128, BL / 64), 256>>>(
        p_xh, p_wkh, kernel_b, p_kmat, BL, HK, CC);

    // join: gather needs wave + kmat + xh
    cudaStreamWaitEvent(0, ev_join, 0);
    gather_kernel<<<BL, 256>>>(p_xh);

    gemm_f16_kernel<128, 128, 4, 2><<<dim3(CC / 128, BL / 128), 256>>>(
        p_yh, p_woh, nullptr, out, BL, CC, CC);

    (void)in_sizes; (void)n_in; (void)out_size;
}